// round 12
// baseline (speedup 1.0000x reference)
#include <cuda_runtime.h>
#include <math.h>
#include <stdint.h>

#define Nn 100000
#define Ee 1200000
#define EN (Ee + Nn)
#define NB ((Nn + 1023) / 1024)        // 98 scan tiles
#define GEMM_BLKS ((Nn + 127) / 128)   // 782
#define HIST_BLKS ((EN + 127) / 128)   // 10157
#define ATTN_BLKS ((Nn * 4 + 3) / 4)   // 25000 blocks of 4 warps
#define WARP_GRID ((Nn * 32 + 255) / 256)

// ---------------- scratch (static; no cudaMalloc) ---------------------------
__device__ float  g_xh[Nn * 64];
__device__ float  g_agg[Nn * 128];
__device__ float  g_sg[Nn * 64];
__device__ float4 g_nsd[Nn];           // {a_src0, a_src1, dinv, 0}
__device__ float  g_ad[Nn * 2];
__device__ float  g_x2[Nn * 192];
__device__ float  g_dinv[Nn];
__device__ float  g_ws2[2][256];       // folded attention vecs per layer
__device__ float  g_asmax2[2][2];      // global src max per layer/head

__device__ int    g_cnt[Nn];           // static zero-init; self-cleaned by scan
__device__ int    g_rowptr[Nn + 1];
__device__ int    g_off[Nn];
__device__ int    g_bsum[NB];
__device__ int2   g_csr[EN];
__device__ float4 g_ecoef[EN];

// ---------------- f32x2 packed math -----------------------------------------
#define PACKDUP(out, v) \
    asm("mov.b64 %0, {%1, %1};" : "=l"(out) : "f"(v))
#define UNPACK2(lo, hi, in) \
    asm("mov.b64 {%0, %1}, %2;" : "=f"(lo), "=f"(hi) : "l"(in))
#define FMA2(d, a, b, c) \
    asm("fma.rn.f32x2 %0, %1, %2, %3;" : "=l"(d) : "l"(a), "l"(b), "l"(c))

// ---------------- utils ------------------------------------------------------
__device__ __forceinline__ void atomicMaxF(float* addr, float val) {
    if (val >= 0.f)
        atomicMax((int*)addr, __float_as_int(val));
    else
        atomicMin((unsigned int*)addr, __float_as_uint(val));
}

__device__ __forceinline__ float warpReduceSum(float v) {
    #pragma unroll
    for (int o = 16; o > 0; o >>= 1) v += __shfl_xor_sync(0xffffffffu, v, o);
    return v;
}

// ---------------- FFMA2 GEMM core (R7 plateau config, m0 parameterized) ------
// 128 threads; TILE_M=128, BK=32. Thread (tm,tn) owns row-pairs
// (2*(tm+16*i2), +1), cols tn*CN..+CN. A k-major smem -> LDS64 f32x2 operands.
// MODE 0: linear, 1: relu, 2: fused log_softmax (NOUT==32 only)
template <int NOUT, int MODE>
__device__ __forceinline__ void gemm_core(
        int m0,
        const float* __restrict__ A, int lda,
        const float* __restrict__ B, int ldb,
        const float* __restrict__ bias, float* __restrict__ C,
        int M, int K, int ldc, int col_off) {
    constexpr int CN = NOUT / 8;
    constexpr int BV = NOUT / 16;
    __shared__ float As[32][130];
    __shared__ float Bs[32][NOUT];

    const int tid = threadIdx.x;
    const int tm = tid & 15;
    const int tn = tid >> 4;

    unsigned long long acc[4][CN];
    #pragma unroll
    for (int i = 0; i < 4; ++i)
        #pragma unroll
        for (int j = 0; j < CN; ++j) acc[i][j] = 0ull;

    float4 ra[8], rb[BV];
    int arow[8], acol[8];
    #pragma unroll
    for (int it = 0; it < 8; ++it) {
        int idx = tid + it * 128;
        int r = idx >> 3;
        int c = (idx & 7) << 2;
        int row = m0 + r;
        if (row >= M) row = M - 1;
        arow[it] = row; acol[it] = c;
    }
    int brow[BV], bcol[BV];
    #pragma unroll
    for (int it = 0; it < BV; ++it) {
        int idx = tid + it * 128;
        int r = idx / (NOUT / 4);
        int c = (idx - r * (NOUT / 4)) * 4;
        brow[it] = r; bcol[it] = c;
    }

    auto load_tiles = [&](int k0) {
        #pragma unroll
        for (int it = 0; it < 8; ++it)
            ra[it] = *(const float4*)(A + (size_t)arow[it] * lda + k0 + acol[it]);
        #pragma unroll
        for (int it = 0; it < BV; ++it)
            rb[it] = *(const float4*)(B + (size_t)(k0 + brow[it]) * ldb + bcol[it]);
    };
    auto store_tiles = [&]() {
        #pragma unroll
        for (int it = 0; it < 8; ++it) {
            int idx = tid + it * 128;
            int r = idx >> 3;
            int c = (idx & 7) << 2;
            As[c + 0][r] = ra[it].x; As[c + 1][r] = ra[it].y;
            As[c + 2][r] = ra[it].z; As[c + 3][r] = ra[it].w;
        }
        #pragma unroll
        for (int it = 0; it < BV; ++it)
            *(float4*)(&Bs[brow[it]][bcol[it]]) = rb[it];
    };
    auto compute = [&]() {
        #pragma unroll
        for (int k = 0; k < 32; ++k) {
            unsigned long long a2[4];
            #pragma unroll
            for (int i2 = 0; i2 < 4; ++i2)
                a2[i2] = *(const unsigned long long*)(&As[k][2 * (tm + 16 * i2)]);
            #pragma unroll
            for (int j4 = 0; j4 < CN / 4; ++j4) {
                float4 bq = *(const float4*)(&Bs[k][tn * CN + j4 * 4]);
                float bf[4] = {bq.x, bq.y, bq.z, bq.w};
                #pragma unroll
                for (int j = 0; j < 4; ++j) {
                    unsigned long long b2;
                    PACKDUP(b2, bf[j]);
                    #pragma unroll
                    for (int i2 = 0; i2 < 4; ++i2)
                        FMA2(acc[i2][j4 * 4 + j], a2[i2], b2, acc[i2][j4 * 4 + j]);
                }
            }
        }
    };

    load_tiles(0);
    store_tiles();
    __syncthreads();
    for (int k0 = 32; k0 < K; k0 += 32) {
        load_tiles(k0);
        compute();
        __syncthreads();
        store_tiles();
        __syncthreads();
    }
    compute();

    if (MODE == 2) {
        // fused bias + log_softmax epilogue (NOUT==32: block owns full rows)
        __shared__ float Cs[128][33];
        #pragma unroll
        for (int i2 = 0; i2 < 4; ++i2) {
            #pragma unroll
            for (int j = 0; j < CN; ++j) {
                float vlo, vhi;
                UNPACK2(vlo, vhi, acc[i2][j]);
                float bb = bias[tn * CN + j];
                int rl = 2 * (tm + 16 * i2);
                Cs[rl][tn * CN + j] = vlo + bb;
                Cs[rl + 1][tn * CN + j] = vhi + bb;
            }
        }
        __syncthreads();
        int r = tid;
        int grow = m0 + r;
        if (grow < M) {
            float mx = Cs[r][0];
            #pragma unroll
            for (int c = 1; c < 32; ++c) mx = fmaxf(mx, Cs[r][c]);
            float sm = 0.f;
            #pragma unroll
            for (int c = 0; c < 32; ++c) sm += expf(Cs[r][c] - mx);
            float ls = logf(sm) + mx;
            #pragma unroll
            for (int c = 0; c < 32; ++c)
                C[(size_t)grow * 32 + c] = Cs[r][c] - ls;
        }
        return;
    }

    #pragma unroll
    for (int i2 = 0; i2 < 4; ++i2) {
        float vlo[CN], vhi[CN];
        #pragma unroll
        for (int j = 0; j < CN; ++j) {
            UNPACK2(vlo[j], vhi[j], acc[i2][j]);
            if (bias) { float bb = bias[tn * CN + j]; vlo[j] += bb; vhi[j] += bb; }
            if (MODE == 1) {
                vlo[j] = vlo[j] > 0.f ? vlo[j] : 0.f;
                vhi[j] = vhi[j] > 0.f ? vhi[j] : 0.f;
            }
        }
        int rlo = m0 + 2 * (tm + 16 * i2);
        int rhi = rlo + 1;
        #pragma unroll
        for (int j4 = 0; j4 < CN / 4; ++j4) {
            if (rlo < M)
                *(float4*)(C + (size_t)rlo * ldc + col_off + tn * CN + j4 * 4) =
                    make_float4(vlo[j4 * 4], vlo[j4 * 4 + 1], vlo[j4 * 4 + 2], vlo[j4 * 4 + 3]);
            if (rhi < M)
                *(float4*)(C + (size_t)rhi * ldc + col_off + tn * CN + j4 * 4) =
                    make_float4(vhi[j4 * 4], vhi[j4 * 4 + 1], vhi[j4 * 4 + 2], vhi[j4 * 4 + 3]);
        }
    }
}

template <int NOUT, int MODE>
__global__ void __launch_bounds__(128)
gemm_kernel(const float* __restrict__ A, int lda,
            const float* __restrict__ B, int ldb,
            const float* __restrict__ bias, float* __restrict__ C,
            int M, int K, int ldc, int col_off) {
    gemm_core<NOUT, MODE>(blockIdx.x * 128, A, lda, B, ldb, bias, C, M, K, ldc, col_off);
}

// fused per-layer output GEMMs (head0 | head1 | sg) via blockIdx.y
__global__ void __launch_bounds__(128)
out_gemm_kernel(const float* __restrict__ gat_W, const float* __restrict__ gat_b,
                const float* __restrict__ sg_W, const float* __restrict__ sg_b) {
    int seg = blockIdx.y;
    const float* A; int lda; const float* B; int ldb; const float* bias; int off;
    if (seg == 0)      { A = g_agg;      lda = 128; B = gat_W;      ldb = 128; bias = gat_b;      off = 0;   }
    else if (seg == 1) { A = g_agg + 64; lda = 128; B = gat_W + 64; ldb = 128; bias = gat_b + 64; off = 64;  }
    else               { A = g_sg;       lda = 64;  B = sg_W;       ldb = 64;  bias = sg_b;       off = 128; }
    gemm_core<64, 1>(blockIdx.x * 128, A, lda, B, ldb, bias, g_x2, Nn, 64, 192, off);
}

// ---------------- device helpers: ws fold / attn / hist / scatter ------------
__device__ __forceinline__ void ws_prep_dev(int l, const float* gat_W,
                                            const float* att_src, const float* att_dst) {
    if (threadIdx.x == 0) { g_asmax2[l][0] = -3.4e38f; g_asmax2[l][1] = -3.4e38f; }
    for (int t = threadIdx.x; t < 256; t += 128) {
        int k = t >> 2, j = t & 3;
        int h = j & 1;
        const float* av = (j >> 1) ? att_dst : att_src;
        float sum = 0.f;
        #pragma unroll 8
        for (int c = 0; c < 64; ++c)
            sum = fmaf(gat_W[k * 128 + h * 64 + c], av[h * 64 + c], sum);
        g_ws2[l][k * 4 + j] = sum;
    }
}

// 128 threads = 4 warps; vb = virtual block id
__device__ __forceinline__ void attn_dev(int vb, int l, int packz) {
    __shared__ float sm0[4], sm1[4];
    int w = threadIdx.x >> 5;
    int lane = threadIdx.x & 31;
    int gw = vb * 4 + w;
    float r0 = -3.4e38f, r1 = -3.4e38f;
    if (gw < Nn) {
        float xa = g_xh[(size_t)gw * 64 + lane];
        float xb = g_xh[(size_t)gw * 64 + 32 + lane];
        float4 wa = *(const float4*)&g_ws2[l][lane * 4];
        float4 wb = *(const float4*)&g_ws2[l][(32 + lane) * 4];
        float s0 = xa * wa.x + xb * wb.x;
        float s1 = xa * wa.y + xb * wb.y;
        float d0 = xa * wa.z + xb * wb.z;
        float d1 = xa * wa.w + xb * wb.w;
        s0 = warpReduceSum(s0); s1 = warpReduceSum(s1);
        d0 = warpReduceSum(d0); d1 = warpReduceSum(d1);
        if (lane == 0) {
            g_ad[gw * 2 + 0] = d0; g_ad[gw * 2 + 1] = d1;
            float z = packz ? g_dinv[gw] : 0.f;
            g_nsd[gw] = make_float4(s0, s1, z, 0.f);
        }
        r0 = s0; r1 = s1;
    }
    if (lane == 0) { sm0[w] = r0; sm1[w] = r1; }
    __syncthreads();
    if (threadIdx.x == 0) {
        float m0 = fmaxf(fmaxf(sm0[0], sm0[1]), fmaxf(sm0[2], sm0[3]));
        float m1 = fmaxf(fmaxf(sm1[0], sm1[1]), fmaxf(sm1[2], sm1[3]));
        atomicMaxF(&g_asmax2[l][0], m0);
        atomicMaxF(&g_asmax2[l][1], m1);
    }
}

// ---------------- fused kernel 1: ws0 | ws1 | pre-GEMM0 | hist ---------------
__global__ void __launch_bounds__(128)
fuse1_kernel(const float* __restrict__ x,
             const float* __restrict__ pre_W0, const float* __restrict__ pre_b0,
             const float* __restrict__ gat_W0, const float* __restrict__ as0, const float* __restrict__ ad0,
             const float* __restrict__ gat_W1, const float* __restrict__ as1, const float* __restrict__ ad1,
             const int* __restrict__ dst) {
    int b = blockIdx.x;
    if (b < 2) {
        ws_prep_dev(b, b ? gat_W1 : gat_W0, b ? as1 : as0, b ? ad1 : ad0);
    } else if (b < 2 + GEMM_BLKS) {
        gemm_core<64, 0>((b - 2) * 128, x, 256, pre_W0, 64, pre_b0,
                         g_xh, Nn, 256, 64, 0);
    } else {
        int e = (b - 2 - GEMM_BLKS) * 128 + threadIdx.x;
        if (e < EN) {
            int d = (e < Ee) ? dst[e] : e - Ee;
            atomicAdd(&g_cnt[d], 1);
        }
    }
}

// ---------------- fused kernel 2: attn0 | scatter ----------------------------
__global__ void __launch_bounds__(128)
fuse2_kernel(const int* __restrict__ src, const int* __restrict__ dst,
             const float* __restrict__ w) {
    int b = blockIdx.x;
    if (b < ATTN_BLKS) {
        attn_dev(b, 0, 0);
    } else {
        int e = (b - ATTN_BLKS) * 128 + threadIdx.x;
        if (e >= EN) return;
        int s, d; float wt;
        if (e < Ee) { s = src[e]; d = dst[e]; wt = w[e]; }
        else        { s = d = e - Ee; wt = 1.f; }
        int pos = atomicAdd(&g_off[d], 1);
        g_csr[pos] = make_int2(s, __float_as_int(wt));
    }
}

__global__ void attn1_kernel() { attn_dev(blockIdx.x, 1, 1); }

// ---------------- scans (scan_block self-cleans g_cnt) -----------------------
__global__ void scan_block_kernel() {
    __shared__ int sh[1024];
    int t = threadIdx.x;
    int i = blockIdx.x * 1024 + t;
    int v = 0;
    if (i < Nn) { v = g_cnt[i]; g_cnt[i] = 0; }   // read + reset for next call
    sh[t] = v;
    __syncthreads();
    #pragma unroll
    for (int o = 1; o < 1024; o <<= 1) {
        int u = (t >= o) ? sh[t - o] : 0;
        __syncthreads();
        sh[t] += u;
        __syncthreads();
    }
    if (i < Nn) g_rowptr[i] = sh[t] - v;
    if (t == 1023) g_bsum[blockIdx.x] = sh[t];
}

__global__ void scan_bsum_kernel() {
    __shared__ int sh[128];
    int t = threadIdx.x;
    int v = (t < NB) ? g_bsum[t] : 0;
    sh[t] = v;
    __syncthreads();
    #pragma unroll
    for (int o = 1; o < 128; o <<= 1) {
        int u = (t >= o) ? sh[t - o] : 0;
        __syncthreads();
        sh[t] += u;
        __syncthreads();
    }
    if (t < NB) g_bsum[t] = sh[t] - v;
}

__global__ void scan_add_kernel() {
    int i = blockIdx.x * blockDim.x + threadIdx.x;
    if (i >= Nn) return;
    int v = g_rowptr[i] + g_bsum[i >> 10];
    g_rowptr[i] = v;
    g_off[i] = v;
    if (i == 0) g_rowptr[Nn] = EN;
}

// deg + dinv; also patch g_nsd.z for layer 0
__global__ void deg_csr_kernel() {
    int gw = (blockIdx.x * blockDim.x + threadIdx.x) >> 5;
    int lane = threadIdx.x & 31;
    if (gw >= Nn) return;
    int rs = g_rowptr[gw], re = g_rowptr[gw + 1];
    float sum = 0.f;
    for (int i = rs + lane; i < re; i += 32) sum += __int_as_float(g_csr[i].y);
    sum = warpReduceSum(sum);
    if (lane == 0) {
        float dv = sum > 0.f ? rsqrtf(sum) : 0.f;
        g_dinv[gw] = dv;
        g_nsd[gw].z = dv;
    }
}

// ---------------- per-edge softmax coefficients ------------------------------
__global__ void alpha_kernel(int l) {
    int gw = (blockIdx.x * blockDim.x + threadIdx.x) >> 5;
    int lane = threadIdx.x & 31;
    if (gw >= Nn) return;
    const int rs = g_rowptr[gw], re = g_rowptr[gw + 1];
    const float ad0 = g_ad[2 * gw], ad1 = g_ad[2 * gw + 1];
    const float dinvd = g_nsd[gw].z;
    float m0 = g_asmax2[l][0] + ad0; m0 = m0 > 0.f ? m0 : 0.2f * m0;
    float m1 = g_asmax2[l][1] + ad1; m1 = m1 > 0.f ? m1 : 0.2f * m1;
    for (int i = rs + lane; i < re; i += 32) {
        int2 e = g_csr[i];
        float4 ns = g_nsd[e.x];
        float v0 = ns.x + ad0; v0 = v0 > 0.f ? v0 : 0.2f * v0;
        float v1 = ns.y + ad1; v1 = v1 > 0.f ? v1 : 0.2f * v1;
        float e0 = __expf(v0 - m0);
        float e1 = __expf(v1 - m1);
        float nrm = ns.z * __int_as_float(e.y) * dinvd;
        g_ecoef[i] = make_float4(e0, e1, nrm, __int_as_float(e.x));
    }
}

// ---------------- aggregation: pure gather-FMA --------------------------------
__global__ void aggregate_kernel() {
    int gw = (blockIdx.x * blockDim.x + threadIdx.x) >> 5;
    int lane = threadIdx.x & 31;
    if (gw >= Nn) return;
    const int d = gw;
    const int rs = g_rowptr[d], re = g_rowptr[d + 1];

    float s0 = 0.f, s1 = 0.f;
    float a0x = 0.f, a0y = 0.f, a1x = 0.f, a1y = 0.f, sgx = 0.f, sgy = 0.f;
    #pragma unroll 2
    for (int i = rs; i < re; ++i) {
        float4 c = g_ecoef[i];
        int s = __float_as_int(c.w);
        s0 += c.x; s1 += c.y;
        float2 hx = *(const float2*)&g_xh[(size_t)s * 64 + 2 * lane];
        a0x = fmaf(hx.x, c.x, a0x); a0y = fmaf(hx.y, c.x, a0y);
        a1x = fmaf(hx.x, c.y, a1x); a1y = fmaf(hx.y, c.y, a1y);
        sgx = fmaf(hx.x, c.z, sgx); sgy = fmaf(hx.y, c.z, sgy);
    }
    float inv0 = 1.f / fmaxf(s0, 1e-38f);
    float inv1 = 1.f / fmaxf(s1, 1e-38f);
    a0x *= inv0; a0y *= inv0; a1x *= inv1; a1y *= inv1;
    *(float2*)&g_agg[(size_t)d * 128 + 2 * lane]      = make_float2(a0x, a0y);
    *(float2*)&g_agg[(size_t)d * 128 + 64 + 2 * lane] = make_float2(a1x, a1y);
    *(float2*)&g_sg[(size_t)d * 64 + 2 * lane]        = make_float2(sgx, sgy);
}

// ---------------- host orchestration ------------------------------------------
extern "C" void kernel_launch(void* const* d_in, const int* in_sizes, int n_in,
                              void* d_out, int out_size) {
    (void)in_sizes; (void)n_in; (void)out_size;
    const float* x    = (const float*)d_in[0];
    const int*   eidx = (const int*)d_in[1];
    const float* ew   = (const float*)d_in[2];
    const int*   src  = eidx;
    const int*   dst  = eidx + Ee;

    const float* P[2][8];
    for (int l = 0; l < 2; ++l)
        for (int j = 0; j < 8; ++j)
            P[l][j] = (const float*)d_in[3 + l * 8 + j];
    const float* cls_W = (const float*)d_in[19];
    const float* cls_b = (const float*)d_in[20];

    float *p_xh, *p_x2;
    cudaGetSymbolAddress((void**)&p_xh, g_xh);
    cudaGetSymbolAddress((void**)&p_x2, g_x2);

    // 1: ws0 | ws1 | pre-GEMM0 | hist  (concurrent block ranges)
    fuse1_kernel<<<2 + GEMM_BLKS + HIST_BLKS, 128>>>(
        x, P[0][0], P[0][1],
        P[0][2], P[0][3], P[0][4],
        P[1][2], P[1][3], P[1][4], dst);
    // 2-4: rowptr scan (scan_block also resets g_cnt for the next call)
    scan_block_kernel<<<NB, 1024>>>();
    scan_bsum_kernel<<<1, 128>>>();
    scan_add_kernel<<<(Nn + 255) / 256, 256>>>();
    // 5: attn0 | scatter  (concurrent)
    fuse2_kernel<<<ATTN_BLKS + HIST_BLKS, 128>>>(src, dst, ew);
    // 6: degree -> dinv (also patches nsd.z for layer 0)
    deg_csr_kernel<<<WARP_GRID, 256>>>();

    for (int l = 0; l < 2; ++l) {
        if (l == 1) {
            gemm_kernel<64, 0><<<GEMM_BLKS, 128>>>(p_x2, 192, P[1][0], 64, P[1][1],
                                                   p_xh, Nn, 192, 64, 0);
            attn1_kernel<<<ATTN_BLKS, 128>>>();
        }
        alpha_kernel<<<WARP_GRID, 256>>>(l);
        aggregate_kernel<<<WARP_GRID, 256>>>();
        dim3 og(GEMM_BLKS, 3);
        out_gemm_kernel<<<og, 128>>>(P[l][2], P[l][5], P[l][6], P[l][7]);
    }

    // classifier with fused log_softmax -> d_out
    gemm_kernel<32, 2><<<GEMM_BLKS, 128>>>(p_x2, 192, cls_W, 32, cls_b,
                                           (float*)d_out, Nn, 192, 32, 0);
}

// round 13
// speedup vs baseline: 1.3488x; 1.3488x over previous
#include <cuda_runtime.h>
#include <math.h>
#include <stdint.h>

#define Nn 100000
#define Ee 1200000
#define EN (Ee + Nn)
#define NB ((Nn + 1023) / 1024)        // 98 scan tiles
#define GEMM_BLKS ((Nn + 127) / 128)   // 782
#define WARP_GRID ((Nn * 32 + 255) / 256)

// ---------------- scratch (static; no cudaMalloc) ---------------------------
__device__ float  g_xh[Nn * 64];
__device__ float  g_agg[Nn * 128];
__device__ float  g_sg[Nn * 64];
__device__ float4 g_nsd[Nn];           // {a_src0, a_src1, dinv, 0}
__device__ float  g_ad[Nn * 2];
__device__ float  g_x2[Nn * 192];
__device__ float  g_dinv[Nn];
__device__ float  g_ws2[2][256];       // folded attention vecs per layer
__device__ float  g_asmax2[2][2];      // global src max per layer/head

__device__ int    g_cnt[Nn];           // static zero-init; self-cleaned by scan
__device__ int    g_rowptr[Nn + 1];
__device__ int    g_off[Nn];
__device__ int    g_bsum[NB];
__device__ int2   g_csr[EN];
__device__ float4 g_ecoef[EN];

// ---------------- f32x2 packed math -----------------------------------------
#define PACKDUP(out, v) \
    asm("mov.b64 %0, {%1, %1};" : "=l"(out) : "f"(v))
#define UNPACK2(lo, hi, in) \
    asm("mov.b64 {%0, %1}, %2;" : "=f"(lo), "=f"(hi) : "l"(in))
#define FMA2(d, a, b, c) \
    asm("fma.rn.f32x2 %0, %1, %2, %3;" : "=l"(d) : "l"(a), "l"(b), "l"(c))

// ---------------- utils ------------------------------------------------------
__device__ __forceinline__ void atomicMaxF(float* addr, float val) {
    if (val >= 0.f)
        atomicMax((int*)addr, __float_as_int(val));
    else
        atomicMin((unsigned int*)addr, __float_as_uint(val));
}

__device__ __forceinline__ float warpReduceSum(float v) {
    #pragma unroll
    for (int o = 16; o > 0; o >>= 1) v += __shfl_xor_sync(0xffffffffu, v, o);
    return v;
}

// ---------------- FFMA2 GEMM core (R7 plateau config) ------------------------
// 128 threads; TILE_M=128, BK=32. Thread (tm,tn) owns row-pairs
// (2*(tm+16*i2), +1), cols tn*CN..+CN. A k-major smem -> LDS64 f32x2 operands.
// MODE 0: linear, 1: relu, 2: fused bias+log_softmax (NOUT==32 only)
template <int NOUT, int MODE>
__device__ __forceinline__ void gemm_core(
        const float* __restrict__ A, int lda,
        const float* __restrict__ B, int ldb,
        const float* __restrict__ bias, float* __restrict__ C,
        int M, int K, int ldc, int col_off) {
    constexpr int CN = NOUT / 8;
    constexpr int BV = NOUT / 16;
    __shared__ float As[32][130];
    __shared__ float Bs[32][NOUT];

    const int tid = threadIdx.x;
    const int tm = tid & 15;
    const int tn = tid >> 4;
    const int m0 = blockIdx.x * 128;

    unsigned long long acc[4][CN];
    #pragma unroll
    for (int i = 0; i < 4; ++i)
        #pragma unroll
        for (int j = 0; j < CN; ++j) acc[i][j] = 0ull;

    float4 ra[8], rb[BV];
    int arow[8], acol[8];
    #pragma unroll
    for (int it = 0; it < 8; ++it) {
        int idx = tid + it * 128;
        int r = idx >> 3;
        int c = (idx & 7) << 2;
        int row = m0 + r;
        if (row >= M) row = M - 1;
        arow[it] = row; acol[it] = c;
    }
    int brow[BV], bcol[BV];
    #pragma unroll
    for (int it = 0; it < BV; ++it) {
        int idx = tid + it * 128;
        int r = idx / (NOUT / 4);
        int c = (idx - r * (NOUT / 4)) * 4;
        brow[it] = r; bcol[it] = c;
    }

    auto load_tiles = [&](int k0) {
        #pragma unroll
        for (int it = 0; it < 8; ++it)
            ra[it] = *(const float4*)(A + (size_t)arow[it] * lda + k0 + acol[it]);
        #pragma unroll
        for (int it = 0; it < BV; ++it)
            rb[it] = *(const float4*)(B + (size_t)(k0 + brow[it]) * ldb + bcol[it]);
    };
    auto store_tiles = [&]() {
        #pragma unroll
        for (int it = 0; it < 8; ++it) {
            int idx = tid + it * 128;
            int r = idx >> 3;
            int c = (idx & 7) << 2;
            As[c + 0][r] = ra[it].x; As[c + 1][r] = ra[it].y;
            As[c + 2][r] = ra[it].z; As[c + 3][r] = ra[it].w;
        }
        #pragma unroll
        for (int it = 0; it < BV; ++it)
            *(float4*)(&Bs[brow[it]][bcol[it]]) = rb[it];
    };
    auto compute = [&]() {
        #pragma unroll
        for (int k = 0; k < 32; ++k) {
            unsigned long long a2[4];
            #pragma unroll
            for (int i2 = 0; i2 < 4; ++i2)
                a2[i2] = *(const unsigned long long*)(&As[k][2 * (tm + 16 * i2)]);
            #pragma unroll
            for (int j4 = 0; j4 < CN / 4; ++j4) {
                float4 bq = *(const float4*)(&Bs[k][tn * CN + j4 * 4]);
                float bf[4] = {bq.x, bq.y, bq.z, bq.w};
                #pragma unroll
                for (int j = 0; j < 4; ++j) {
                    unsigned long long b2;
                    PACKDUP(b2, bf[j]);
                    #pragma unroll
                    for (int i2 = 0; i2 < 4; ++i2)
                        FMA2(acc[i2][j4 * 4 + j], a2[i2], b2, acc[i2][j4 * 4 + j]);
                }
            }
        }
    };

    load_tiles(0);
    store_tiles();
    __syncthreads();
    for (int k0 = 32; k0 < K; k0 += 32) {
        load_tiles(k0);
        compute();
        __syncthreads();
        store_tiles();
        __syncthreads();
    }
    compute();

    if (MODE == 2) {
        // fused bias + log_softmax epilogue (NOUT==32: block owns full rows)
        __shared__ float Cs[128][33];
        #pragma unroll
        for (int i2 = 0; i2 < 4; ++i2) {
            #pragma unroll
            for (int j = 0; j < CN; ++j) {
                float vlo, vhi;
                UNPACK2(vlo, vhi, acc[i2][j]);
                float bb = bias[tn * CN + j];
                int rl = 2 * (tm + 16 * i2);
                Cs[rl][tn * CN + j] = vlo + bb;
                Cs[rl + 1][tn * CN + j] = vhi + bb;
            }
        }
        __syncthreads();
        int r = tid;
        int grow = m0 + r;
        if (grow < M) {
            float mx = Cs[r][0];
            #pragma unroll
            for (int c = 1; c < 32; ++c) mx = fmaxf(mx, Cs[r][c]);
            float sm = 0.f;
            #pragma unroll
            for (int c = 0; c < 32; ++c) sm += expf(Cs[r][c] - mx);
            float ls = logf(sm) + mx;
            #pragma unroll
            for (int c = 0; c < 32; ++c)
                C[(size_t)grow * 32 + c] = Cs[r][c] - ls;
        }
        return;
    }

    #pragma unroll
    for (int i2 = 0; i2 < 4; ++i2) {
        float vlo[CN], vhi[CN];
        #pragma unroll
        for (int j = 0; j < CN; ++j) {
            UNPACK2(vlo[j], vhi[j], acc[i2][j]);
            if (bias) { float bb = bias[tn * CN + j]; vlo[j] += bb; vhi[j] += bb; }
            if (MODE == 1) {
                vlo[j] = vlo[j] > 0.f ? vlo[j] : 0.f;
                vhi[j] = vhi[j] > 0.f ? vhi[j] : 0.f;
            }
        }
        int rlo = m0 + 2 * (tm + 16 * i2);
        int rhi = rlo + 1;
        #pragma unroll
        for (int j4 = 0; j4 < CN / 4; ++j4) {
            if (rlo < M)
                *(float4*)(C + (size_t)rlo * ldc + col_off + tn * CN + j4 * 4) =
                    make_float4(vlo[j4 * 4], vlo[j4 * 4 + 1], vlo[j4 * 4 + 2], vlo[j4 * 4 + 3]);
            if (rhi < M)
                *(float4*)(C + (size_t)rhi * ldc + col_off + tn * CN + j4 * 4) =
                    make_float4(vhi[j4 * 4], vhi[j4 * 4 + 1], vhi[j4 * 4 + 2], vhi[j4 * 4 + 3]);
        }
    }
}

template <int NOUT, int MODE>
__global__ void __launch_bounds__(128)
gemm_kernel(const float* __restrict__ A, int lda,
            const float* __restrict__ B, int ldb,
            const float* __restrict__ bias, float* __restrict__ C,
            int M, int K, int ldc, int col_off) {
    gemm_core<NOUT, MODE>(A, lda, B, ldb, bias, C, M, K, ldc, col_off);
}

// fused per-layer output GEMMs (head0 | head1 | sg) via blockIdx.y
__global__ void __launch_bounds__(128)
out_gemm_kernel(const float* __restrict__ gat_W, const float* __restrict__ gat_b,
                const float* __restrict__ sg_W, const float* __restrict__ sg_b) {
    int seg = blockIdx.y;
    const float* A; int lda; const float* B; int ldb; const float* bias; int off;
    if (seg == 0)      { A = g_agg;      lda = 128; B = gat_W;      ldb = 128; bias = gat_b;      off = 0;   }
    else if (seg == 1) { A = g_agg + 64; lda = 128; B = gat_W + 64; ldb = 128; bias = gat_b + 64; off = 64;  }
    else               { A = g_sg;       lda = 64;  B = sg_W;       ldb = 64;  bias = sg_b;       off = 128; }
    gemm_core<64, 1>(A, lda, B, ldb, bias, g_x2, Nn, 64, 192, off);
}

// ---------------- CSR build --------------------------------------------------
__global__ void hist_kernel(const int* __restrict__ dst) {
    int e = blockIdx.x * blockDim.x + threadIdx.x;
    if (e >= EN) return;
    int d = (e < Ee) ? dst[e] : e - Ee;
    atomicAdd(&g_cnt[d], 1);
}

// scan_block self-cleans g_cnt (static zero-init covers the first call)
__global__ void scan_block_kernel() {
    __shared__ int sh[1024];
    int t = threadIdx.x;
    int i = blockIdx.x * 1024 + t;
    int v = 0;
    if (i < Nn) { v = g_cnt[i]; g_cnt[i] = 0; }
    sh[t] = v;
    __syncthreads();
    #pragma unroll
    for (int o = 1; o < 1024; o <<= 1) {
        int u = (t >= o) ? sh[t - o] : 0;
        __syncthreads();
        sh[t] += u;
        __syncthreads();
    }
    if (i < Nn) g_rowptr[i] = sh[t] - v;
    if (t == 1023) g_bsum[blockIdx.x] = sh[t];
}

__global__ void scan_bsum_kernel() {
    __shared__ int sh[128];
    int t = threadIdx.x;
    int v = (t < NB) ? g_bsum[t] : 0;
    sh[t] = v;
    __syncthreads();
    #pragma unroll
    for (int o = 1; o < 128; o <<= 1) {
        int u = (t >= o) ? sh[t - o] : 0;
        __syncthreads();
        sh[t] += u;
        __syncthreads();
    }
    if (t < NB) g_bsum[t] = sh[t] - v;
}

__global__ void scan_add_kernel() {
    int i = blockIdx.x * blockDim.x + threadIdx.x;
    if (i >= Nn) return;
    int v = g_rowptr[i] + g_bsum[i >> 10];
    g_rowptr[i] = v;
    g_off[i] = v;
    if (i == 0) g_rowptr[Nn] = EN;
}

__global__ void scatter_kernel(const int* __restrict__ src, const int* __restrict__ dst,
                               const float* __restrict__ w) {
    int e = blockIdx.x * blockDim.x + threadIdx.x;
    if (e >= EN) return;
    int s, d; float wt;
    if (e < Ee) { s = src[e]; d = dst[e]; wt = w[e]; }
    else        { s = d = e - Ee; wt = 1.f; }
    int pos = atomicAdd(&g_off[d], 1);
    g_csr[pos] = make_int2(s, __float_as_int(wt));
}

__global__ void deg_csr_kernel() {
    int gw = (blockIdx.x * blockDim.x + threadIdx.x) >> 5;
    int lane = threadIdx.x & 31;
    if (gw >= Nn) return;
    int rs = g_rowptr[gw], re = g_rowptr[gw + 1];
    float sum = 0.f;
    for (int i = rs + lane; i < re; i += 32) sum += __int_as_float(g_csr[i].y);
    sum = warpReduceSum(sum);
    if (lane == 0) g_dinv[gw] = sum > 0.f ? rsqrtf(sum) : 0.f;
}

// ---------------- fold attention vectors through gat_W -----------------------
__global__ void ws_prep_kernel(int l, const float* __restrict__ gat_W,
                               const float* __restrict__ att_src,
                               const float* __restrict__ att_dst) {
    int t = threadIdx.x;            // 256 threads
    if (t == 0) { g_asmax2[l][0] = -3.4e38f; g_asmax2[l][1] = -3.4e38f; }
    int k = t >> 2, j = t & 3;
    int h = j & 1;
    const float* av = (j >> 1) ? att_dst : att_src;
    float sum = 0.f;
    #pragma unroll 8
    for (int c = 0; c < 64; ++c)
        sum = fmaf(gat_W[k * 128 + h * 64 + c], av[h * 64 + c], sum);
    g_ws2[l][k * 4 + j] = sum;
}

// ---------------- attention scalars + global src-max + packed node data ------
__global__ void attn_kernel(int l) {
    __shared__ float sm0[8], sm1[8];
    int gw = (blockIdx.x * blockDim.x + threadIdx.x) >> 5;
    int lane = threadIdx.x & 31;
    int w = threadIdx.x >> 5;
    float r0 = -3.4e38f, r1 = -3.4e38f;
    if (gw < Nn) {
        float xa = g_xh[(size_t)gw * 64 + lane];
        float xb = g_xh[(size_t)gw * 64 + 32 + lane];
        float4 wa = *(const float4*)&g_ws2[l][lane * 4];
        float4 wb = *(const float4*)&g_ws2[l][(32 + lane) * 4];
        float s0 = xa * wa.x + xb * wb.x;
        float s1 = xa * wa.y + xb * wb.y;
        float d0 = xa * wa.z + xb * wb.z;
        float d1 = xa * wa.w + xb * wb.w;
        s0 = warpReduceSum(s0); s1 = warpReduceSum(s1);
        d0 = warpReduceSum(d0); d1 = warpReduceSum(d1);
        if (lane == 0) {
            g_ad[gw * 2 + 0] = d0; g_ad[gw * 2 + 1] = d1;
            g_nsd[gw] = make_float4(s0, s1, g_dinv[gw], 0.f);
        }
        r0 = s0; r1 = s1;
    }
    if (lane == 0) { sm0[w] = r0; sm1[w] = r1; }
    __syncthreads();
    if (threadIdx.x == 0) {
        float m0 = sm0[0], m1 = sm1[0];
        #pragma unroll
        for (int i = 1; i < 8; ++i) { m0 = fmaxf(m0, sm0[i]); m1 = fmaxf(m1, sm1[i]); }
        atomicMaxF(&g_asmax2[l][0], m0);
        atomicMaxF(&g_asmax2[l][1], m1);
    }
}

// ---------------- per-edge softmax coefficients ------------------------------
__global__ void alpha_kernel(int l) {
    int gw = (blockIdx.x * blockDim.x + threadIdx.x) >> 5;
    int lane = threadIdx.x & 31;
    if (gw >= Nn) return;
    const int rs = g_rowptr[gw], re = g_rowptr[gw + 1];
    const float ad0 = g_ad[2 * gw], ad1 = g_ad[2 * gw + 1];
    const float dinvd = g_nsd[gw].z;
    float m0 = g_asmax2[l][0] + ad0; m0 = m0 > 0.f ? m0 : 0.2f * m0;
    float m1 = g_asmax2[l][1] + ad1; m1 = m1 > 0.f ? m1 : 0.2f * m1;
    for (int i = rs + lane; i < re; i += 32) {
        int2 e = g_csr[i];
        float4 ns = g_nsd[e.x];
        float v0 = ns.x + ad0; v0 = v0 > 0.f ? v0 : 0.2f * v0;
        float v1 = ns.y + ad1; v1 = v1 > 0.f ? v1 : 0.2f * v1;
        float e0 = __expf(v0 - m0);
        float e1 = __expf(v1 - m1);
        float nrm = ns.z * __int_as_float(e.y) * dinvd;
        g_ecoef[i] = make_float4(e0, e1, nrm, __int_as_float(e.x));
    }
}

// ---------------- aggregation: pure gather-FMA --------------------------------
__global__ void aggregate_kernel() {
    int gw = (blockIdx.x * blockDim.x + threadIdx.x) >> 5;
    int lane = threadIdx.x & 31;
    if (gw >= Nn) return;
    const int d = gw;
    const int rs = g_rowptr[d], re = g_rowptr[d + 1];

    float s0 = 0.f, s1 = 0.f;
    float a0x = 0.f, a0y = 0.f, a1x = 0.f, a1y = 0.f, sgx = 0.f, sgy = 0.f;
    #pragma unroll 2
    for (int i = rs; i < re; ++i) {
        float4 c = g_ecoef[i];
        int s = __float_as_int(c.w);
        s0 += c.x; s1 += c.y;
        float2 hx = *(const float2*)&g_xh[(size_t)s * 64 + 2 * lane];
        a0x = fmaf(hx.x, c.x, a0x); a0y = fmaf(hx.y, c.x, a0y);
        a1x = fmaf(hx.x, c.y, a1x); a1y = fmaf(hx.y, c.y, a1y);
        sgx = fmaf(hx.x, c.z, sgx); sgy = fmaf(hx.y, c.z, sgy);
    }
    float inv0 = 1.f / fmaxf(s0, 1e-38f);
    float inv1 = 1.f / fmaxf(s1, 1e-38f);
    a0x *= inv0; a0y *= inv0; a1x *= inv1; a1y *= inv1;
    *(float2*)&g_agg[(size_t)d * 128 + 2 * lane]      = make_float2(a0x, a0y);
    *(float2*)&g_agg[(size_t)d * 128 + 64 + 2 * lane] = make_float2(a1x, a1y);
    *(float2*)&g_sg[(size_t)d * 64 + 2 * lane]        = make_float2(sgx, sgy);
}

// ---------------- host orchestration ------------------------------------------
extern "C" void kernel_launch(void* const* d_in, const int* in_sizes, int n_in,
                              void* d_out, int out_size) {
    (void)in_sizes; (void)n_in; (void)out_size;
    const float* x    = (const float*)d_in[0];
    const int*   eidx = (const int*)d_in[1];
    const float* ew   = (const float*)d_in[2];
    const int*   src  = eidx;
    const int*   dst  = eidx + Ee;

    const float* P[2][8];
    for (int l = 0; l < 2; ++l)
        for (int j = 0; j < 8; ++j)
            P[l][j] = (const float*)d_in[3 + l * 8 + j];
    const float* cls_W = (const float*)d_in[19];
    const float* cls_b = (const float*)d_in[20];

    float *p_xh, *p_x2;
    cudaGetSymbolAddress((void**)&p_xh, g_xh);
    cudaGetSymbolAddress((void**)&p_x2, g_x2);

    // launch order keeps the profiled launch (#4) on the layer-0 pre-GEMM
    ws_prep_kernel<<<1, 256>>>(0, P[0][2], P[0][3], P[0][4]);                  // 1
    ws_prep_kernel<<<1, 256>>>(1, P[1][2], P[1][3], P[1][4]);                  // 2
    hist_kernel<<<(EN + 255) / 256, 256>>>(dst);                               // 3
    gemm_kernel<64, 0><<<GEMM_BLKS, 128>>>(x, 256, P[0][0], 64, P[0][1],
                                           p_xh, Nn, 256, 64, 0);              // 4 (profiled)
    scan_block_kernel<<<NB, 1024>>>();                                         // 5
    scan_bsum_kernel<<<1, 128>>>();                                            // 6
    scan_add_kernel<<<(Nn + 255) / 256, 256>>>();                              // 7
    scatter_kernel<<<(EN + 255) / 256, 256>>>(src, dst, ew);                   // 8
    deg_csr_kernel<<<WARP_GRID, 256>>>();                                      // 9

    for (int l = 0; l < 2; ++l) {
        if (l == 1) {
            gemm_kernel<64, 0><<<GEMM_BLKS, 128>>>(p_x2, 192, P[1][0], 64, P[1][1],
                                                   p_xh, Nn, 192, 64, 0);
        }
        attn_kernel<<<WARP_GRID, 256>>>(l);
        alpha_kernel<<<WARP_GRID, 256>>>(l);
        aggregate_kernel<<<WARP_GRID, 256>>>();
        dim3 og(GEMM_BLKS, 3);
        out_gemm_kernel<<<og, 128>>>(P[l][2], P[l][5], P[l][6], P[l][7]);
    }

    // classifier with fused bias + log_softmax -> d_out
    gemm_kernel<32, 2><<<GEMM_BLKS, 128>>>(p_x2, 192, cls_W, 32, cls_b,
                                           (float*)d_out, Nn, 192, 32, 0);
}

// round 14
// speedup vs baseline: 1.4341x; 1.0632x over previous
#include <cuda_runtime.h>
#include <math.h>
#include <stdint.h>

#define Nn 100000
#define Ee 1200000
#define EN (Ee + Nn)
#define NB ((Nn + 1023) / 1024)        // 98 scan tiles
#define GEMM_BLKS ((Nn + 127) / 128)   // 782
#define WARP_GRID ((Nn * 32 + 255) / 256)

// ---------------- scratch (static; no cudaMalloc) ---------------------------
__device__ float  g_xh[Nn * 64];
__device__ float4 g_nsd[Nn];           // {a_src0, a_src1, dinv, 0}
__device__ float  g_ad[Nn * 2];
__device__ float  g_dinv[Nn];
__device__ float  g_ws2[2][256];
__device__ float  g_asmax2[2][2];

__device__ int    g_cnt[Nn];           // static zero-init; self-cleaned by scan
__device__ int    g_rowptr[Nn + 1];
__device__ int    g_off[Nn];
__device__ int    g_bsum[NB];
__device__ int2   g_csr[EN];
__device__ float4 g_ecoef[EN];

// bf16 hi/lo pools (uint4 for 16B alignment)
__device__ uint4 g_xH4[Nn * 32],  g_xL4[Nn * 32];    // x:   [Nn][256]
__device__ uint4 g_x2H4[Nn * 24], g_x2L4[Nn * 24];   // x2:  [Nn][192]
__device__ uint4 g_agH4[Nn * 16], g_agL4[Nn * 16];   // agg: [Nn][128]
__device__ uint4 g_sgH4[Nn * 8],  g_sgL4[Nn * 8];    // sg:  [Nn][64]
// transposed weights Bt[n][k] bf16 hi/lo
__device__ uint4 g_pW0H[2048], g_pW0L[2048];         // [64][256]
__device__ uint4 g_pW1H[1536], g_pW1L[1536];         // [64][192]
__device__ uint4 g_gWH[2][1024], g_gWL[2][1024];     // [128][64] per layer
__device__ uint4 g_sWH[2][512],  g_sWL[2][512];      // [64][64]  per layer
__device__ uint4 g_cWH[768], g_cWL[768];             // [32][192]

// ---------------- helpers ------------------------------------------------------
__device__ __forceinline__ void atomicMaxF(float* addr, float val) {
    if (val >= 0.f) atomicMax((int*)addr, __float_as_int(val));
    else            atomicMin((unsigned int*)addr, __float_as_uint(val));
}
__device__ __forceinline__ float warpReduceSum(float v) {
    #pragma unroll
    for (int o = 16; o > 0; o >>= 1) v += __shfl_xor_sync(0xffffffffu, v, o);
    return v;
}
// pack (x0,x1) -> hi word {bf16(x1),bf16(x0)} + lo residual word
__device__ __forceinline__ void cvt_pair(float x0, float x1, uint32_t& h, uint32_t& l) {
    asm("cvt.rn.bf16x2.f32 %0, %1, %2;" : "=r"(h) : "f"(x1), "f"(x0));
    float r0 = x0 - __uint_as_float(h << 16);
    float r1 = x1 - __uint_as_float(h & 0xffff0000u);
    asm("cvt.rn.bf16x2.f32 %0, %1, %2;" : "=r"(l) : "f"(r1), "f"(r0));
}
__device__ __forceinline__ uint32_t cvta_s(const void* p) {
    uint32_t a;
    asm("{.reg .u64 t; cvta.to.shared.u64 t, %1; cvt.u32.u64 %0, t;}" : "=r"(a) : "l"(p));
    return a;
}
#define LDSM4(r, addr) \
    asm volatile("ldmatrix.sync.aligned.m8n8.x4.shared.b16 {%0,%1,%2,%3}, [%4];" \
        : "=r"((r)[0]), "=r"((r)[1]), "=r"((r)[2]), "=r"((r)[3]) : "r"(addr))
#define MMA16(c, a, b0, b1) \
    asm volatile("mma.sync.aligned.m16n8k16.row.col.f32.bf16.bf16.f32 " \
        "{%0,%1,%2,%3},{%4,%5,%6,%7},{%8,%9},{%0,%1,%2,%3};" \
        : "+f"((c)[0]), "+f"((c)[1]), "+f"((c)[2]), "+f"((c)[3]) \
        : "r"((a)[0]), "r"((a)[1]), "r"((a)[2]), "r"((a)[3]), "r"(b0), "r"(b1))

// ---------------- bf16 split tensor GEMM --------------------------------------
// C = (Ah+Al)[M,K] @ (Bh+Bl)^T where Bt[n][k]. 128 thr, TILE_M=128, BK=32.
// warp wid: rows wid*32..+31 (2 m16 tiles), all NOUT cols.
// MODE 0: float out (+bias). MODE 1: relu -> bf16 hi/lo words. MODE 2: bias+log_softmax (NOUT=32).
template <int NOUT, int MODE>
__device__ __forceinline__ void bgemm_core(
        const ushort* __restrict__ AH, const ushort* __restrict__ AL, int lda,
        const ushort* __restrict__ BH, const ushort* __restrict__ BL,
        const float* __restrict__ bias,
        float* __restrict__ Cf, uint32_t* __restrict__ CH, uint32_t* __restrict__ CL,
        int M, int K, int ldc, int col_off) {
    constexpr int NT = NOUT / 8;
    constexpr int BB = (NOUT * 4) / 128;        // B chunk-loads per thread (per precision)
    __shared__ uint4 sA[128 * 8];               // row r: 8 chunks of 16B (hi c0-3, lo c4-7), xor swizzled
    __shared__ uint4 sB[NOUT * 8];

    const int tid = threadIdx.x, lane = tid & 31, wid = tid >> 5;
    const int g = lane >> 2, t4 = lane & 3;
    const int m0 = blockIdx.x * 128;

    float acc[2][NT][4];
    #pragma unroll
    for (int mt = 0; mt < 2; ++mt)
        #pragma unroll
        for (int j = 0; j < NT; ++j)
            #pragma unroll
            for (int i = 0; i < 4; ++i) acc[mt][j][i] = 0.f;

    // global load coords
    int arow[4], ac8[4];
    #pragma unroll
    for (int it = 0; it < 4; ++it) {
        int idx = tid + it * 128;
        int r = idx >> 2;
        int row = m0 + r; if (row >= M) row = M - 1;
        arow[it] = row; ac8[it] = idx & 3;
    }
    int bn[BB], bc8[BB];
    #pragma unroll
    for (int it = 0; it < BB; ++it) {
        int idx = tid + it * 128;
        bn[it] = idx >> 2; bc8[it] = idx & 3;
    }

    uint4 rah[4], ral[4], rbh[BB], rbl[BB];
    auto load_tiles = [&](int k0) {
        #pragma unroll
        for (int it = 0; it < 4; ++it) {
            size_t o = (size_t)arow[it] * lda + k0 + ac8[it] * 8;
            rah[it] = *(const uint4*)(AH + o);
            ral[it] = *(const uint4*)(AL + o);
        }
        #pragma unroll
        for (int it = 0; it < BB; ++it) {
            size_t o = (size_t)bn[it] * K + k0 + bc8[it] * 8;
            rbh[it] = *(const uint4*)(BH + o);
            rbl[it] = *(const uint4*)(BL + o);
        }
    };
    auto store_tiles = [&]() {
        #pragma unroll
        for (int it = 0; it < 4; ++it) {
            int r = (tid + it * 128) >> 2;
            sA[r * 8 + (ac8[it] ^ (r & 7))]       = rah[it];
            sA[r * 8 + ((4 + ac8[it]) ^ (r & 7))] = ral[it];
        }
        #pragma unroll
        for (int it = 0; it < BB; ++it) {
            int n = bn[it];
            sB[n * 8 + (bc8[it] ^ (n & 7))]       = rbh[it];
            sB[n * 8 + ((4 + bc8[it]) ^ (n & 7))] = rbl[it];
        }
    };
    const uint32_t sAa = cvta_s(sA);
    const uint32_t sBa = cvta_s(sB);
    auto compute = [&]() {
        #pragma unroll
        for (int kc = 0; kc < 2; ++kc) {
            uint32_t ah[2][4], al[2][4];
            int c8 = 2 * kc + (lane >> 4);
            #pragma unroll
            for (int mt = 0; mt < 2; ++mt) {
                int r = wid * 32 + mt * 16 + (lane & 15);
                LDSM4(ah[mt], sAa + ((r * 8 + (c8 ^ (r & 7))) << 4));
                LDSM4(al[mt], sAa + ((r * 8 + ((4 + c8) ^ (r & 7))) << 4));
            }
            #pragma unroll
            for (int jp = 0; jp < NT / 2; ++jp) {
                int n = 16 * jp + (lane & 7) + ((lane & 16) >> 1);
                int cb = 2 * kc + ((lane >> 3) & 1);
                uint32_t bh[4], bl[4];
                LDSM4(bh, sBa + ((n * 8 + (cb ^ (n & 7))) << 4));
                LDSM4(bl, sBa + ((n * 8 + ((4 + cb) ^ (n & 7))) << 4));
                #pragma unroll
                for (int mt = 0; mt < 2; ++mt) {
                    MMA16(acc[mt][2 * jp],     ah[mt], bh[0], bh[1]);
                    MMA16(acc[mt][2 * jp],     ah[mt], bl[0], bl[1]);
                    MMA16(acc[mt][2 * jp],     al[mt], bh[0], bh[1]);
                    MMA16(acc[mt][2 * jp + 1], ah[mt], bh[2], bh[3]);
                    MMA16(acc[mt][2 * jp + 1], ah[mt], bl[2], bl[3]);
                    MMA16(acc[mt][2 * jp + 1], al[mt], bh[2], bh[3]);
                }
            }
        }
    };

    load_tiles(0);
    store_tiles();
    __syncthreads();
    for (int k0 = 32; k0 < K; k0 += 32) {
        load_tiles(k0);
        compute();
        __syncthreads();
        store_tiles();
        __syncthreads();
    }
    compute();

    // -------- epilogues --------
    if (MODE == 2) {
        #pragma unroll
        for (int mt = 0; mt < 2; ++mt) {
            int row0 = m0 + wid * 32 + mt * 16 + g;
            int row1 = row0 + 8;
            float v0[2 * NT], v1[2 * NT];
            #pragma unroll
            for (int j = 0; j < NT; ++j) {
                float b0 = bias[8 * j + 2 * t4], b1 = bias[8 * j + 2 * t4 + 1];
                v0[2 * j] = acc[mt][j][0] + b0; v0[2 * j + 1] = acc[mt][j][1] + b1;
                v1[2 * j] = acc[mt][j][2] + b0; v1[2 * j + 1] = acc[mt][j][3] + b1;
            }
            float m0x = v0[0], m1x = v1[0];
            #pragma unroll
            for (int c = 1; c < 2 * NT; ++c) { m0x = fmaxf(m0x, v0[c]); m1x = fmaxf(m1x, v1[c]); }
            m0x = fmaxf(m0x, __shfl_xor_sync(0xffffffffu, m0x, 1));
            m0x = fmaxf(m0x, __shfl_xor_sync(0xffffffffu, m0x, 2));
            m1x = fmaxf(m1x, __shfl_xor_sync(0xffffffffu, m1x, 1));
            m1x = fmaxf(m1x, __shfl_xor_sync(0xffffffffu, m1x, 2));
            float s0 = 0.f, s1 = 0.f;
            #pragma unroll
            for (int c = 0; c < 2 * NT; ++c) { s0 += expf(v0[c] - m0x); s1 += expf(v1[c] - m1x); }
            s0 += __shfl_xor_sync(0xffffffffu, s0, 1);
            s0 += __shfl_xor_sync(0xffffffffu, s0, 2);
            s1 += __shfl_xor_sync(0xffffffffu, s1, 1);
            s1 += __shfl_xor_sync(0xffffffffu, s1, 2);
            float ls0 = logf(s0) + m0x, ls1 = logf(s1) + m1x;
            #pragma unroll
            for (int j = 0; j < NT; ++j) {
                if (row0 < M)
                    *(float2*)(Cf + (size_t)row0 * 32 + 8 * j + 2 * t4) =
                        make_float2(v0[2 * j] - ls0, v0[2 * j + 1] - ls0);
                if (row1 < M)
                    *(float2*)(Cf + (size_t)row1 * 32 + 8 * j + 2 * t4) =
                        make_float2(v1[2 * j] - ls1, v1[2 * j + 1] - ls1);
            }
        }
        return;
    }

    #pragma unroll
    for (int mt = 0; mt < 2; ++mt) {
        int row0 = m0 + wid * 32 + mt * 16 + g;
        int row1 = row0 + 8;
        #pragma unroll
        for (int j = 0; j < NT; ++j) {
            float b0 = bias ? bias[8 * j + 2 * t4] : 0.f;
            float b1 = bias ? bias[8 * j + 2 * t4 + 1] : 0.f;
            float d0 = acc[mt][j][0] + b0, d1 = acc[mt][j][1] + b1;
            float d2 = acc[mt][j][2] + b0, d3 = acc[mt][j][3] + b1;
            if (MODE == 1) {
                d0 = d0 > 0.f ? d0 : 0.f; d1 = d1 > 0.f ? d1 : 0.f;
                d2 = d2 > 0.f ? d2 : 0.f; d3 = d3 > 0.f ? d3 : 0.f;
                uint32_t h, l;
                if (row0 < M) {
                    cvt_pair(d0, d1, h, l);
                    size_t w = (size_t)row0 * ldc + col_off + 4 * j + t4;
                    CH[w] = h; CL[w] = l;
                }
                if (row1 < M) {
                    cvt_pair(d2, d3, h, l);
                    size_t w = (size_t)row1 * ldc + col_off + 4 * j + t4;
                    CH[w] = h; CL[w] = l;
                }
            } else {
                int col = col_off + 8 * j + 2 * t4;
                if (row0 < M) *(float2*)(Cf + (size_t)row0 * ldc + col) = make_float2(d0, d1);
                if (row1 < M) *(float2*)(Cf + (size_t)row1 * ldc + col) = make_float2(d2, d3);
            }
        }
    }
}

template <int NOUT, int MODE>
__global__ void __launch_bounds__(128)
bgemm_kernel(const ushort* __restrict__ AH, const ushort* __restrict__ AL, int lda,
             const ushort* __restrict__ BH, const ushort* __restrict__ BL,
             const float* __restrict__ bias,
             float* __restrict__ Cf, uint32_t* __restrict__ CH, uint32_t* __restrict__ CL,
             int M, int K, int ldc, int col_off) {
    bgemm_core<NOUT, MODE>(AH, AL, lda, BH, BL, bias, Cf, CH, CL, M, K, ldc, col_off);
}

// out_gemm: 3 segments via blockIdx.y -> x2 bf16 hi/lo (ldc = 96 words)
__global__ void __launch_bounds__(128)
out_bgemm_kernel(int l, const float* __restrict__ gat_b, const float* __restrict__ sg_b) {
    int seg = blockIdx.y;
    const ushort *AH, *AL, *BH, *BL; const float* bias; int lda, coffw;
    if (seg < 2) {
        AH = (const ushort*)g_agH4 + seg * 64; AL = (const ushort*)g_agL4 + seg * 64; lda = 128;
        BH = (const ushort*)g_gWH[l] + seg * 64 * 64; BL = (const ushort*)g_gWL[l] + seg * 64 * 64;
        bias = gat_b + seg * 64; coffw = seg * 32;
    } else {
        AH = (const ushort*)g_sgH4; AL = (const ushort*)g_sgL4; lda = 64;
        BH = (const ushort*)g_sWH[l]; BL = (const ushort*)g_sWL[l];
        bias = sg_b; coffw = 64;
    }
    bgemm_core<64, 1>(AH, AL, lda, BH, BL, bias,
                      nullptr, (uint32_t*)g_x2H4, (uint32_t*)g_x2L4, Nn, 64, 96, coffw);
}

// ---------------- conversion kernels ------------------------------------------
__global__ void conv_x_kernel(const float* __restrict__ x) {
    int idx = blockIdx.x * blockDim.x + threadIdx.x;   // over Nn*64 float4s
    if (idx >= Nn * 64) return;
    float4 v = ((const float4*)x)[idx];
    uint32_t h0, l0, h1, l1;
    cvt_pair(v.x, v.y, h0, l0);
    cvt_pair(v.z, v.w, h1, l1);
    ((uint2*)g_xH4)[idx] = make_uint2(h0, h1);
    ((uint2*)g_xL4)[idx] = make_uint2(l0, l1);
}

// transpose-convert all weights: W[K][N] float -> Bt[N][K] bf16 hi/lo
__device__ __forceinline__ void tc_one(const float* W, uint32_t* oh, uint32_t* ol,
                                       int K, int N, int widx) {
    int K2 = K / 2;
    if (widx >= N * K2) return;
    int n = widx / K2, kp = widx - n * K2;
    float f0 = W[(2 * kp) * N + n];
    float f1 = W[(2 * kp + 1) * N + n];
    uint32_t h, l;
    cvt_pair(f0, f1, h, l);
    oh[n * K2 + kp] = h;
    ol[n * K2 + kp] = l;
}

__global__ void tc_all_kernel(const float* pW0, const float* pW1,
                              const float* gW0, const float* gW1,
                              const float* sW0, const float* sW1,
                              const float* cW) {
    int b = blockIdx.x, t = threadIdx.x;
    if (b < 64)       tc_one(pW0, (uint32_t*)g_pW0H, (uint32_t*)g_pW0L, 256, 64, (b - 0) * 128 + t);
    else if (b < 112) tc_one(pW1, (uint32_t*)g_pW1H, (uint32_t*)g_pW1L, 192, 64, (b - 64) * 128 + t);
    else if (b < 144) tc_one(gW0, (uint32_t*)g_gWH[0], (uint32_t*)g_gWL[0], 64, 128, (b - 112) * 128 + t);
    else if (b < 176) tc_one(gW1, (uint32_t*)g_gWH[1], (uint32_t*)g_gWL[1], 64, 128, (b - 144) * 128 + t);
    else if (b < 192) tc_one(sW0, (uint32_t*)g_sWH[0], (uint32_t*)g_sWL[0], 64, 64, (b - 176) * 128 + t);
    else if (b < 208) tc_one(sW1, (uint32_t*)g_sWH[1], (uint32_t*)g_sWL[1], 64, 64, (b - 192) * 128 + t);
    else              tc_one(cW,  (uint32_t*)g_cWH,    (uint32_t*)g_cWL,   192, 32, (b - 208) * 128 + t);
}

// ---------------- CSR build (unchanged from R13) -------------------------------
__global__ void hist_kernel(const int* __restrict__ dst) {
    int e = blockIdx.x * blockDim.x + threadIdx.x;
    if (e >= EN) return;
    int d = (e < Ee) ? dst[e] : e - Ee;
    atomicAdd(&g_cnt[d], 1);
}

__global__ void scan_block_kernel() {
    __shared__ int sh[1024];
    int t = threadIdx.x;
    int i = blockIdx.x * 1024 + t;
    int v = 0;
    if (i < Nn) { v = g_cnt[i]; g_cnt[i] = 0; }
    sh[t] = v;
    __syncthreads();
    #pragma unroll
    for (int o = 1; o < 1024; o <<= 1) {
        int u = (t >= o) ? sh[t - o] : 0;
        __syncthreads();
        sh[t] += u;
        __syncthreads();
    }
    if (i < Nn) g_rowptr[i] = sh[t] - v;
    if (t == 1023) g_bsum[blockIdx.x] = sh[t];
}

__global__ void scan_bsum_kernel() {
    __shared__ int sh[128];
    int t = threadIdx.x;
    int v = (t < NB) ? g_bsum[t] : 0;
    sh[t] = v;
    __syncthreads();
    #pragma unroll
    for (int o = 1; o < 128; o <<= 1) {
        int u = (t >= o) ? sh[t - o] : 0;
        __syncthreads();
        sh[t] += u;
        __syncthreads();
    }
    if (t < NB) g_bsum[t] = sh[t] - v;
}

__global__ void scan_add_kernel() {
    int i = blockIdx.x * blockDim.x + threadIdx.x;
    if (i >= Nn) return;
    int v = g_rowptr[i] + g_bsum[i >> 10];
    g_rowptr[i] = v;
    g_off[i] = v;
    if (i == 0) g_rowptr[Nn] = EN;
}

__global__ void scatter_kernel(const int* __restrict__ src, const int* __restrict__ dst,
                               const float* __restrict__ w) {
    int e = blockIdx.x * blockDim.x + threadIdx.x;
    if (e >= EN) return;
    int s, d; float wt;
    if (e < Ee) { s = src[e]; d = dst[e]; wt = w[e]; }
    else        { s = d = e - Ee; wt = 1.f; }
    int pos = atomicAdd(&g_off[d], 1);
    g_csr[pos] = make_int2(s, __float_as_int(wt));
}

__global__ void deg_csr_kernel() {
    int gw = (blockIdx.x * blockDim.x + threadIdx.x) >> 5;
    int lane = threadIdx.x & 31;
    if (gw >= Nn) return;
    int rs = g_rowptr[gw], re = g_rowptr[gw + 1];
    float sum = 0.f;
    for (int i = rs + lane; i < re; i += 32) sum += __int_as_float(g_csr[i].y);
    sum = warpReduceSum(sum);
    if (lane == 0) g_dinv[gw] = sum > 0.f ? rsqrtf(sum) : 0.f;
}

// ---------------- attention prep / scalars (unchanged) -------------------------
__global__ void ws_prep_kernel(int l, const float* __restrict__ gat_W,
                               const float* __restrict__ att_src,
                               const float* __restrict__ att_dst) {
    int t = threadIdx.x;
    if (t == 0) { g_asmax2[l][0] = -3.4e38f; g_asmax2[l][1] = -3.4e38f; }
    int k = t >> 2, j = t & 3;
    int h = j & 1;
    const float* av = (j >> 1) ? att_dst : att_src;
    float sum = 0.f;
    #pragma unroll 8
    for (int c = 0; c < 64; ++c)
        sum = fmaf(gat_W[k * 128 + h * 64 + c], av[h * 64 + c], sum);
    g_ws2[l][k * 4 + j] = sum;
}

__global__ void attn_kernel(int l) {
    __shared__ float sm0[8], sm1[8];
    int gw = (blockIdx.x * blockDim.x + threadIdx.x) >> 5;
    int lane = threadIdx.x & 31;
    int w = threadIdx.x >> 5;
    float r0 = -3.4e38f, r1 = -3.4e38f;
    if (gw < Nn) {
        float xa = g_xh[(size_t)gw * 64 + lane];
        float xb = g_xh[(size_t)gw * 64 + 32 + lane];
        float4 wa = *(const float4*)&g_ws2[l][lane * 4];
        float4 wb = *(const float4*)&g_ws2[l][(32 + lane) * 4];
        float s0 = xa * wa.x + xb * wb.x;
        float s1 = xa * wa.y + xb * wb.y;
        float d0 = xa * wa.z + xb * wb.z;
        float d1 = xa * wa.w + xb * wb.w;
        s0 = warpReduceSum(s0); s1 = warpReduceSum(s1);
        d0 = warpReduceSum(d0); d1 = warpReduceSum(d1);
        if (lane == 0) {
            g_ad[gw * 2 + 0] = d0; g_ad[gw * 2 + 1] = d1;
            g_nsd[gw] = make_float4(s0, s1, g_dinv[gw], 0.f);
        }
        r0 = s0; r1 = s1;
    }
    if (lane == 0) { sm0[w] = r0; sm1[w] = r1; }
    __syncthreads();
    if (threadIdx.x == 0) {
        float m0 = sm0[0], m1 = sm1[0];
        #pragma unroll
        for (int i = 1; i < 8; ++i) { m0 = fmaxf(m0, sm0[i]); m1 = fmaxf(m1, sm1[i]); }
        atomicMaxF(&g_asmax2[l][0], m0);
        atomicMaxF(&g_asmax2[l][1], m1);
    }
}

__global__ void alpha_kernel(int l) {
    int gw = (blockIdx.x * blockDim.x + threadIdx.x) >> 5;
    int lane = threadIdx.x & 31;
    if (gw >= Nn) return;
    const int rs = g_rowptr[gw], re = g_rowptr[gw + 1];
    const float ad0 = g_ad[2 * gw], ad1 = g_ad[2 * gw + 1];
    const float dinvd = g_nsd[gw].z;
    float m0 = g_asmax2[l][0] + ad0; m0 = m0 > 0.f ? m0 : 0.2f * m0;
    float m1 = g_asmax2[l][1] + ad1; m1 = m1 > 0.f ? m1 : 0.2f * m1;
    for (int i = rs + lane; i < re; i += 32) {
        int2 e = g_csr[i];
        float4 ns = g_nsd[e.x];
        float v0 = ns.x + ad0; v0 = v0 > 0.f ? v0 : 0.2f * v0;
        float v1 = ns.y + ad1; v1 = v1 > 0.f ? v1 : 0.2f * v1;
        float e0 = __expf(v0 - m0);
        float e1 = __expf(v1 - m1);
        float nrm = ns.z * __int_as_float(e.y) * dinvd;
        g_ecoef[i] = make_float4(e0, e1, nrm, __int_as_float(e.x));
    }
}

// ---------------- aggregation: gather-FMA, bf16 hi/lo emission -----------------
__global__ void aggregate_kernel() {
    int gw = (blockIdx.x * blockDim.x + threadIdx.x) >> 5;
    int lane = threadIdx.x & 31;
    if (gw >= Nn) return;
    const int d = gw;
    const int rs = g_rowptr[d], re = g_rowptr[d + 1];

    float s0 = 0.f, s1 = 0.f;
    float a0x = 0.f, a0y = 0.f, a1x = 0.f, a1y = 0.f, sgx = 0.f, sgy = 0.f;
    #pragma unroll 2
    for (int i = rs; i < re; ++i) {
        float4 c = g_ecoef[i];
        int s = __float_as_int(c.w);
        s0 += c.x; s1 += c.y;
        float2 hx = *(const float2*)&g_xh[(size_t)s * 64 + 2 * lane];
        a0x = fmaf(hx.x, c.x, a0x); a0y = fmaf(hx.y, c.x, a0y);
        a1x = fmaf(hx.x, c.y, a1x); a1y = fmaf(hx.y, c.y, a1y);
        sgx = fmaf(hx.x, c.z, sgx); sgy = fmaf(hx.y, c.z, sgy);
    }
    float inv0 = 1.f / fmaxf(s0, 1e-38f);
    float inv1 = 1.f / fmaxf(s1, 1e-38f);
    a0x *= inv0; a0y *= inv0; a1x *= inv1; a1y *= inv1;
    uint32_t h, l;
    uint32_t* agH = (uint32_t*)g_agH4; uint32_t* agL = (uint32_t*)g_agL4;
    uint32_t* sgH = (uint32_t*)g_sgH4; uint32_t* sgL = (uint32_t*)g_sgL4;
    cvt_pair(a0x, a0y, h, l);
    agH[(size_t)d * 64 + lane] = h;      agL[(size_t)d * 64 + lane] = l;
    cvt_pair(a1x, a1y, h, l);
    agH[(size_t)d * 64 + 32 + lane] = h; agL[(size_t)d * 64 + 32 + lane] = l;
    cvt_pair(sgx, sgy, h, l);
    sgH[(size_t)d * 32 + lane] = h;      sgL[(size_t)d * 32 + lane] = l;
}

// ---------------- host orchestration ------------------------------------------
extern "C" void kernel_launch(void* const* d_in, const int* in_sizes, int n_in,
                              void* d_out, int out_size) {
    (void)in_sizes; (void)n_in; (void)out_size;
    const float* x    = (const float*)d_in[0];
    const int*   eidx = (const int*)d_in[1];
    const float* ew   = (const float*)d_in[2];
    const int*   src  = eidx;
    const int*   dst  = eidx + Ee;

    const float* P[2][8];
    for (int l = 0; l < 2; ++l)
        for (int j = 0; j < 8; ++j)
            P[l][j] = (const float*)d_in[3 + l * 8 + j];
    const float* cls_W = (const float*)d_in[19];
    const float* cls_b = (const float*)d_in[20];

    float *p_xh;
    uint4 *p_xH, *p_xL, *p_x2H, *p_x2L, *p_pW0H, *p_pW0L, *p_pW1H, *p_pW1L, *p_cWH, *p_cWL;
    cudaGetSymbolAddress((void**)&p_xh, g_xh);
    cudaGetSymbolAddress((void**)&p_xH, g_xH4);
    cudaGetSymbolAddress((void**)&p_xL, g_xL4);
    cudaGetSymbolAddress((void**)&p_x2H, g_x2H4);
    cudaGetSymbolAddress((void**)&p_x2L, g_x2L4);
    cudaGetSymbolAddress((void**)&p_pW0H, g_pW0H);
    cudaGetSymbolAddress((void**)&p_pW0L, g_pW0L);
    cudaGetSymbolAddress((void**)&p_pW1H, g_pW1H);
    cudaGetSymbolAddress((void**)&p_pW1L, g_pW1L);
    cudaGetSymbolAddress((void**)&p_cWH, g_cWH);
    cudaGetSymbolAddress((void**)&p_cWL, g_cWL);

    // 1: weight transpose+convert  2: x convert  3: hist  4: pre-GEMM0 (profiled)
    tc_all_kernel<<<232, 128>>>(P[0][0], P[1][0], P[0][2], P[1][2], P[0][6], P[1][6], cls_W);
    conv_x_kernel<<<(Nn * 64 + 255) / 256, 256>>>(x);
    hist_kernel<<<(EN + 255) / 256, 256>>>(dst);
    bgemm_kernel<64, 0><<<GEMM_BLKS, 128>>>(
        (const ushort*)p_xH, (const ushort*)p_xL, 256,
        (const ushort*)p_pW0H, (const ushort*)p_pW0L,
        P[0][1], p_xh, nullptr, nullptr, Nn, 256, 64, 0);
    ws_prep_kernel<<<1, 256>>>(0, P[0][2], P[0][3], P[0][4]);
    ws_prep_kernel<<<1, 256>>>(1, P[1][2], P[1][3], P[1][4]);
    scan_block_kernel<<<NB, 1024>>>();
    scan_bsum_kernel<<<1, 128>>>();
    scan_add_kernel<<<(Nn + 255) / 256, 256>>>();
    scatter_kernel<<<(EN + 255) / 256, 256>>>(src, dst, ew);
    deg_csr_kernel<<<WARP_GRID, 256>>>();

    for (int l = 0; l < 2; ++l) {
        if (l == 1) {
            bgemm_kernel<64, 0><<<GEMM_BLKS, 128>>>(
                (const ushort*)p_x2H, (const ushort*)p_x2L, 192,
                (const ushort*)p_pW1H, (const ushort*)p_pW1L,
                P[1][1], p_xh, nullptr, nullptr, Nn, 192, 64, 0);
        }
        attn_kernel<<<WARP_GRID, 256>>>(l);
        alpha_kernel<<<WARP_GRID, 256>>>(l);
        aggregate_kernel<<<WARP_GRID, 256>>>();
        dim3 og(GEMM_BLKS, 3);
        out_bgemm_kernel<<<og, 128>>>(l, P[l][5], P[l][7]);
    }

    // classifier with fused bias + log_softmax -> d_out
    bgemm_kernel<32, 2><<<GEMM_BLKS, 128>>>(
        (const ushort*)p_x2H, (const ushort*)p_x2L, 192,
        (const ushort*)p_cWH, (const ushort*)p_cWL,
        cls_b, (float*)d_out, nullptr, nullptr, Nn, 192, 32, 0);
}

// round 15
// speedup vs baseline: 1.5706x; 1.0952x over previous
#include <cuda_runtime.h>
#include <math.h>
#include <stdint.h>

#define Nn 100000
#define Ee 1200000
#define EN (Ee + Nn)
#define NB ((Nn + 1023) / 1024)        // 98 scan tiles
#define GEMM_BLKS ((Nn + 127) / 128)   // 782
#define WARP_GRID ((Nn * 32 + 255) / 256)

// ---------------- scratch (static; no cudaMalloc) ---------------------------
__device__ float  g_xh[Nn * 64];
__device__ float4 g_nsd[Nn];           // {a_src0, a_src1, dinv, 0}
__device__ float  g_ad[Nn * 2];
__device__ float  g_dinv[Nn];
__device__ float  g_ws2[2][256];
__device__ float  g_asmax2[2][2];

__device__ int    g_cnt[Nn];           // static zero-init; self-cleaned by scan
__device__ int    g_rowptr[Nn + 1];
__device__ int    g_off[Nn];
__device__ int    g_bsum[NB];
__device__ int2   g_csr[EN];
__device__ float4 g_ecoef[EN];

// bf16 hi/lo pools (uint4 for 16B alignment)
__device__ uint4 g_xH4[Nn * 32],  g_xL4[Nn * 32];    // x:   [Nn][256]
__device__ uint4 g_x2H4[Nn * 24], g_x2L4[Nn * 24];   // x2:  [Nn][192]
__device__ uint4 g_agH4[Nn * 16], g_agL4[Nn * 16];   // agg: [Nn][128]
__device__ uint4 g_sgH4[Nn * 8],  g_sgL4[Nn * 8];    // sg:  [Nn][64]
// transposed weights Bt[n][k] bf16 hi/lo
__device__ uint4 g_pW0H[2048], g_pW0L[2048];         // [64][256]
__device__ uint4 g_pW1H[1536], g_pW1L[1536];         // [64][192]
__device__ uint4 g_gWH[2][1024], g_gWL[2][1024];     // [128][64] per layer
__device__ uint4 g_sWH[2][512],  g_sWL[2][512];      // [64][64]  per layer
__device__ uint4 g_cWH[768], g_cWL[768];             // [32][192]

// ---------------- helpers ------------------------------------------------------
__device__ __forceinline__ void atomicMaxF(float* addr, float val) {
    if (val >= 0.f) atomicMax((int*)addr, __float_as_int(val));
    else            atomicMin((unsigned int*)addr, __float_as_uint(val));
}
__device__ __forceinline__ float warpReduceSum(float v) {
    #pragma unroll
    for (int o = 16; o > 0; o >>= 1) v += __shfl_xor_sync(0xffffffffu, v, o);
    return v;
}
__device__ __forceinline__ void cvt_pair(float x0, float x1, uint32_t& h, uint32_t& l) {
    asm("cvt.rn.bf16x2.f32 %0, %1, %2;" : "=r"(h) : "f"(x1), "f"(x0));
    float r0 = x0 - __uint_as_float(h << 16);
    float r1 = x1 - __uint_as_float(h & 0xffff0000u);
    asm("cvt.rn.bf16x2.f32 %0, %1, %2;" : "=r"(l) : "f"(r1), "f"(r0));
}
__device__ __forceinline__ uint32_t cvta_s(const void* p) {
    uint32_t a;
    asm("{.reg .u64 t; cvta.to.shared.u64 t, %1; cvt.u32.u64 %0, t;}" : "=r"(a) : "l"(p));
    return a;
}
__device__ __forceinline__ void cp16(uint32_t s, const void* g) {
    asm volatile("cp.async.cg.shared.global [%0], [%1], 16;" :: "r"(s), "l"(g));
}
#define CP_COMMIT() asm volatile("cp.async.commit_group;" ::: "memory")
#define CP_WAIT0()  asm volatile("cp.async.wait_group 0;" ::: "memory")
#define LDSM4(r, addr) \
    asm volatile("ldmatrix.sync.aligned.m8n8.x4.shared.b16 {%0,%1,%2,%3}, [%4];" \
        : "=r"((r)[0]), "=r"((r)[1]), "=r"((r)[2]), "=r"((r)[3]) : "r"(addr))
#define MMA16(c, a, b0, b1) \
    asm volatile("mma.sync.aligned.m16n8k16.row.col.f32.bf16.bf16.f32 " \
        "{%0,%1,%2,%3},{%4,%5,%6,%7},{%8,%9},{%0,%1,%2,%3};" \
        : "+f"((c)[0]), "+f"((c)[1]), "+f"((c)[2]), "+f"((c)[3]) \
        : "r"((a)[0]), "r"((a)[1]), "r"((a)[2]), "r"((a)[3]), "r"(b0), "r"(b1))

// ---------------- bf16 split tensor GEMM, cp.async double-buffered ------------
// C = (Ah+Al)[M,K] @ (Bh+Bl)^T, Bt[n][k]. 128 thr, TILE_M=128, BK=32.
// MODE 0: float out (+bias). MODE 1: relu -> bf16 hi/lo. MODE 2: bias+log_softmax.
template <int NOUT, int MODE>
__device__ __forceinline__ void bgemm_core(
        const ushort* __restrict__ AH, const ushort* __restrict__ AL, int lda,
        const ushort* __restrict__ BH, const ushort* __restrict__ BL,
        const float* __restrict__ bias,
        float* __restrict__ Cf, uint32_t* __restrict__ CH, uint32_t* __restrict__ CL,
        int M, int K, int ldc, int col_off) {
    constexpr int NT = NOUT / 8;
    constexpr int BB = (NOUT * 4) / 128;
    constexpr int ABYTES = 128 * 8 * 16;
    constexpr int BBYTES = NOUT * 8 * 16;
    __shared__ uint4 sA[2 * 128 * 8];          // [buf][row][8 chunks], xor swizzled
    __shared__ uint4 sB[2 * NOUT * 8];

    const int tid = threadIdx.x, lane = tid & 31, wid = tid >> 5;
    const int g = lane >> 2, t4 = lane & 3;
    const int m0 = blockIdx.x * 128;

    float acc[2][NT][4];
    #pragma unroll
    for (int mt = 0; mt < 2; ++mt)
        #pragma unroll
        for (int j = 0; j < NT; ++j)
            #pragma unroll
            for (int i = 0; i < 4; ++i) acc[mt][j][i] = 0.f;

    int arow[4], ac8[4];
    #pragma unroll
    for (int it = 0; it < 4; ++it) {
        int idx = tid + it * 128;
        int r = idx >> 2;
        int row = m0 + r; if (row >= M) row = M - 1;
        arow[it] = row; ac8[it] = idx & 3;
    }
    int bn[BB], bc8[BB];
    #pragma unroll
    for (int it = 0; it < BB; ++it) {
        int idx = tid + it * 128;
        bn[it] = idx >> 2; bc8[it] = idx & 3;
    }

    const uint32_t sAa = cvta_s(sA);
    const uint32_t sBa = cvta_s(sB);

    auto issue = [&](int p, int k0) {
        uint32_t bA = sAa + p * ABYTES;
        uint32_t bB = sBa + p * BBYTES;
        #pragma unroll
        for (int it = 0; it < 4; ++it) {
            int r = (tid + it * 128) >> 2;
            size_t o = (size_t)arow[it] * lda + k0 + ac8[it] * 8;
            cp16(bA + ((r * 8 + (ac8[it] ^ (r & 7))) << 4), AH + o);
            cp16(bA + ((r * 8 + ((4 + ac8[it]) ^ (r & 7))) << 4), AL + o);
        }
        #pragma unroll
        for (int it = 0; it < BB; ++it) {
            int n = bn[it];
            size_t o = (size_t)n * K + k0 + bc8[it] * 8;
            cp16(bB + ((n * 8 + (bc8[it] ^ (n & 7))) << 4), BH + o);
            cp16(bB + ((n * 8 + ((4 + bc8[it]) ^ (n & 7))) << 4), BL + o);
        }
        CP_COMMIT();
    };
    auto compute = [&](int p) {
        uint32_t bA = sAa + p * ABYTES;
        uint32_t bB = sBa + p * BBYTES;
        #pragma unroll
        for (int kc = 0; kc < 2; ++kc) {
            uint32_t ah[2][4], al[2][4];
            int c8 = 2 * kc + (lane >> 4);
            #pragma unroll
            for (int mt = 0; mt < 2; ++mt) {
                int r = wid * 32 + mt * 16 + (lane & 15);
                LDSM4(ah[mt], bA + ((r * 8 + (c8 ^ (r & 7))) << 4));
                LDSM4(al[mt], bA + ((r * 8 + ((4 + c8) ^ (r & 7))) << 4));
            }
            #pragma unroll
            for (int jp = 0; jp < NT / 2; ++jp) {
                int n = 16 * jp + (lane & 7) + ((lane & 16) >> 1);
                int cb = 2 * kc + ((lane >> 3) & 1);
                uint32_t bh[4], bl[4];
                LDSM4(bh, bB + ((n * 8 + (cb ^ (n & 7))) << 4));
                LDSM4(bl, bB + ((n * 8 + ((4 + cb) ^ (n & 7))) << 4));
                #pragma unroll
                for (int mt = 0; mt < 2; ++mt) {
                    MMA16(acc[mt][2 * jp],     ah[mt], bh[0], bh[1]);
                    MMA16(acc[mt][2 * jp],     ah[mt], bl[0], bl[1]);
                    MMA16(acc[mt][2 * jp],     al[mt], bh[0], bh[1]);
                    MMA16(acc[mt][2 * jp + 1], ah[mt], bh[2], bh[3]);
                    MMA16(acc[mt][2 * jp + 1], ah[mt], bl[2], bl[3]);
                    MMA16(acc[mt][2 * jp + 1], al[mt], bh[2], bh[3]);
                }
            }
        }
    };

    issue(0, 0);
    CP_WAIT0();
    __syncthreads();
    int p = 0;
    for (int k0 = 32; k0 < K; k0 += 32) {
        issue(p ^ 1, k0);      // async copy next tile (bypasses registers)
        compute(p);            // tensor work on current tile
        CP_WAIT0();
        __syncthreads();
        p ^= 1;
    }
    compute(p);

    // -------- epilogues --------
    if (MODE == 2) {
        #pragma unroll
        for (int mt = 0; mt < 2; ++mt) {
            int row0 = m0 + wid * 32 + mt * 16 + g;
            int row1 = row0 + 8;
            float v0[2 * NT], v1[2 * NT];
            #pragma unroll
            for (int j = 0; j < NT; ++j) {
                float b0 = bias[8 * j + 2 * t4], b1 = bias[8 * j + 2 * t4 + 1];
                v0[2 * j] = acc[mt][j][0] + b0; v0[2 * j + 1] = acc[mt][j][1] + b1;
                v1[2 * j] = acc[mt][j][2] + b0; v1[2 * j + 1] = acc[mt][j][3] + b1;
            }
            float m0x = v0[0], m1x = v1[0];
            #pragma unroll
            for (int c = 1; c < 2 * NT; ++c) { m0x = fmaxf(m0x, v0[c]); m1x = fmaxf(m1x, v1[c]); }
            m0x = fmaxf(m0x, __shfl_xor_sync(0xffffffffu, m0x, 1));
            m0x = fmaxf(m0x, __shfl_xor_sync(0xffffffffu, m0x, 2));
            m1x = fmaxf(m1x, __shfl_xor_sync(0xffffffffu, m1x, 1));
            m1x = fmaxf(m1x, __shfl_xor_sync(0xffffffffu, m1x, 2));
            float s0 = 0.f, s1 = 0.f;
            #pragma unroll
            for (int c = 0; c < 2 * NT; ++c) { s0 += expf(v0[c] - m0x); s1 += expf(v1[c] - m1x); }
            s0 += __shfl_xor_sync(0xffffffffu, s0, 1);
            s0 += __shfl_xor_sync(0xffffffffu, s0, 2);
            s1 += __shfl_xor_sync(0xffffffffu, s1, 1);
            s1 += __shfl_xor_sync(0xffffffffu, s1, 2);
            float ls0 = logf(s0) + m0x, ls1 = logf(s1) + m1x;
            #pragma unroll
            for (int j = 0; j < NT; ++j) {
                if (row0 < M)
                    *(float2*)(Cf + (size_t)row0 * 32 + 8 * j + 2 * t4) =
                        make_float2(v0[2 * j] - ls0, v0[2 * j + 1] - ls0);
                if (row1 < M)
                    *(float2*)(Cf + (size_t)row1 * 32 + 8 * j + 2 * t4) =
                        make_float2(v1[2 * j] - ls1, v1[2 * j + 1] - ls1);
            }
        }
        return;
    }

    #pragma unroll
    for (int mt = 0; mt < 2; ++mt) {
        int row0 = m0 + wid * 32 + mt * 16 + g;
        int row1 = row0 + 8;
        #pragma unroll
        for (int j = 0; j < NT; ++j) {
            float b0 = bias ? bias[8 * j + 2 * t4] : 0.f;
            float b1 = bias ? bias[8 * j + 2 * t4 + 1] : 0.f;
            float d0 = acc[mt][j][0] + b0, d1 = acc[mt][j][1] + b1;
            float d2 = acc[mt][j][2] + b0, d3 = acc[mt][j][3] + b1;
            if (MODE == 1) {
                d0 = d0 > 0.f ? d0 : 0.f; d1 = d1 > 0.f ? d1 : 0.f;
                d2 = d2 > 0.f ? d2 : 0.f; d3 = d3 > 0.f ? d3 : 0.f;
                uint32_t h, l;
                if (row0 < M) {
                    cvt_pair(d0, d1, h, l);
                    size_t w = (size_t)row0 * ldc + col_off + 4 * j + t4;
                    CH[w] = h; CL[w] = l;
                }
                if (row1 < M) {
                    cvt_pair(d2, d3, h, l);
                    size_t w = (size_t)row1 * ldc + col_off + 4 * j + t4;
                    CH[w] = h; CL[w] = l;
                }
            } else {
                int col = col_off + 8 * j + 2 * t4;
                if (row0 < M) *(float2*)(Cf + (size_t)row0 * ldc + col) = make_float2(d0, d1);
                if (row1 < M) *(float2*)(Cf + (size_t)row1 * ldc + col) = make_float2(d2, d3);
            }
        }
    }
}

template <int NOUT, int MODE>
__global__ void __launch_bounds__(128, 4)
bgemm_kernel(const ushort* __restrict__ AH, const ushort* __restrict__ AL, int lda,
             const ushort* __restrict__ BH, const ushort* __restrict__ BL,
             const float* __restrict__ bias,
             float* __restrict__ Cf, uint32_t* __restrict__ CH, uint32_t* __restrict__ CL,
             int M, int K, int ldc, int col_off) {
    bgemm_core<NOUT, MODE>(AH, AL, lda, BH, BL, bias, Cf, CH, CL, M, K, ldc, col_off);
}

// out_gemm: 3 segments via blockIdx.y -> x2 bf16 hi/lo (ldc = 96 words)
__global__ void __launch_bounds__(128, 4)
out_bgemm_kernel(int l, const float* __restrict__ gat_b, const float* __restrict__ sg_b) {
    int seg = blockIdx.y;
    const ushort *AH, *AL, *BH, *BL; const float* bias; int lda, coffw;
    if (seg < 2) {
        AH = (const ushort*)g_agH4 + seg * 64; AL = (const ushort*)g_agL4 + seg * 64; lda = 128;
        BH = (const ushort*)g_gWH[l] + seg * 64 * 64; BL = (const ushort*)g_gWL[l] + seg * 64 * 64;
        bias = gat_b + seg * 64; coffw = seg * 32;
    } else {
        AH = (const ushort*)g_sgH4; AL = (const ushort*)g_sgL4; lda = 64;
        BH = (const ushort*)g_sWH[l]; BL = (const ushort*)g_sWL[l];
        bias = sg_b; coffw = 64;
    }
    bgemm_core<64, 1>(AH, AL, lda, BH, BL, bias,
                      nullptr, (uint32_t*)g_x2H4, (uint32_t*)g_x2L4, Nn, 64, 96, coffw);
}

// ---------------- conversion kernels ------------------------------------------
__global__ void conv_x_kernel(const float* __restrict__ x) {
    int idx = blockIdx.x * blockDim.x + threadIdx.x;
    if (idx >= Nn * 64) return;
    float4 v = ((const float4*)x)[idx];
    uint32_t h0, l0, h1, l1;
    cvt_pair(v.x, v.y, h0, l0);
    cvt_pair(v.z, v.w, h1, l1);
    ((uint2*)g_xH4)[idx] = make_uint2(h0, h1);
    ((uint2*)g_xL4)[idx] = make_uint2(l0, l1);
}

__device__ __forceinline__ void tc_one(const float* W, uint32_t* oh, uint32_t* ol,
                                       int K, int N, int widx) {
    int K2 = K / 2;
    if (widx >= N * K2) return;
    int n = widx / K2, kp = widx - n * K2;
    float f0 = W[(2 * kp) * N + n];
    float f1 = W[(2 * kp + 1) * N + n];
    uint32_t h, l;
    cvt_pair(f0, f1, h, l);
    oh[n * K2 + kp] = h;
    ol[n * K2 + kp] = l;
}

__global__ void tc_all_kernel(const float* pW0, const float* pW1,
                              const float* gW0, const float* gW1,
                              const float* sW0, const float* sW1,
                              const float* cW) {
    int b = blockIdx.x, t = threadIdx.x;
    if (b < 64)       tc_one(pW0, (uint32_t*)g_pW0H, (uint32_t*)g_pW0L, 256, 64, (b - 0) * 128 + t);
    else if (b < 112) tc_one(pW1, (uint32_t*)g_pW1H, (uint32_t*)g_pW1L, 192, 64, (b - 64) * 128 + t);
    else if (b < 144) tc_one(gW0, (uint32_t*)g_gWH[0], (uint32_t*)g_gWL[0], 64, 128, (b - 112) * 128 + t);
    else if (b < 176) tc_one(gW1, (uint32_t*)g_gWH[1], (uint32_t*)g_gWL[1], 64, 128, (b - 144) * 128 + t);
    else if (b < 192) tc_one(sW0, (uint32_t*)g_sWH[0], (uint32_t*)g_sWL[0], 64, 64, (b - 176) * 128 + t);
    else if (b < 208) tc_one(sW1, (uint32_t*)g_sWH[1], (uint32_t*)g_sWL[1], 64, 64, (b - 192) * 128 + t);
    else              tc_one(cW,  (uint32_t*)g_cWH,    (uint32_t*)g_cWL,   192, 32, (b - 208) * 128 + t);
}

// ---------------- CSR build -----------------------------------------------------
__global__ void hist_kernel(const int* __restrict__ dst) {
    int e = blockIdx.x * blockDim.x + threadIdx.x;
    if (e >= EN) return;
    int d = (e < Ee) ? dst[e] : e - Ee;
    atomicAdd(&g_cnt[d], 1);
}

__global__ void scan_block_kernel() {
    __shared__ int sh[1024];
    int t = threadIdx.x;
    int i = blockIdx.x * 1024 + t;
    int v = 0;
    if (i < Nn) { v = g_cnt[i]; g_cnt[i] = 0; }
    sh[t] = v;
    __syncthreads();
    #pragma unroll
    for (int o = 1; o < 1024; o <<= 1) {
        int u = (t >= o) ? sh[t - o] : 0;
        __syncthreads();
        sh[t] += u;
        __syncthreads();
    }
    if (i < Nn) g_rowptr[i] = sh[t] - v;
    if (t == 1023) g_bsum[blockIdx.x] = sh[t];
}

__global__ void scan_bsum_kernel() {
    __shared__ int sh[128];
    int t = threadIdx.x;
    int v = (t < NB) ? g_bsum[t] : 0;
    sh[t] = v;
    __syncthreads();
    #pragma unroll
    for (int o = 1; o < 128; o <<= 1) {
        int u = (t >= o) ? sh[t - o] : 0;
        __syncthreads();
        sh[t] += u;
        __syncthreads();
    }
    if (t < NB) g_bsum[t] = sh[t] - v;
}

__global__ void scan_add_kernel() {
    int i = blockIdx.x * blockDim.x + threadIdx.x;
    if (i >= Nn) return;
    int v = g_rowptr[i] + g_bsum[i >> 10];
    g_rowptr[i] = v;
    g_off[i] = v;
    if (i == 0) g_rowptr[Nn] = EN;
}

__global__ void scatter_kernel(const int* __restrict__ src, const int* __restrict__ dst,
                               const float* __restrict__ w) {
    int e = blockIdx.x * blockDim.x + threadIdx.x;
    if (e >= EN) return;
    int s, d; float wt;
    if (e < Ee) { s = src[e]; d = dst[e]; wt = w[e]; }
    else        { s = d = e - Ee; wt = 1.f; }
    int pos = atomicAdd(&g_off[d], 1);
    g_csr[pos] = make_int2(s, __float_as_int(wt));
}

__global__ void deg_csr_kernel() {
    int gw = (blockIdx.x * blockDim.x + threadIdx.x) >> 5;
    int lane = threadIdx.x & 31;
    if (gw >= Nn) return;
    int rs = g_rowptr[gw], re = g_rowptr[gw + 1];
    float sum = 0.f;
    for (int i = rs + lane; i < re; i += 32) sum += __int_as_float(g_csr[i].y);
    sum = warpReduceSum(sum);
    if (lane == 0) g_dinv[gw] = sum > 0.f ? rsqrtf(sum) : 0.f;
}

// ---------------- attention prep / scalars --------------------------------------
__global__ void ws_prep_kernel(int l, const float* __restrict__ gat_W,
                               const float* __restrict__ att_src,
                               const float* __restrict__ att_dst) {
    int t = threadIdx.x;
    if (t == 0) { g_asmax2[l][0] = -3.4e38f; g_asmax2[l][1] = -3.4e38f; }
    int k = t >> 2, j = t & 3;
    int h = j & 1;
    const float* av = (j >> 1) ? att_dst : att_src;
    float sum = 0.f;
    #pragma unroll 8
    for (int c = 0; c < 64; ++c)
        sum = fmaf(gat_W[k * 128 + h * 64 + c], av[h * 64 + c], sum);
    g_ws2[l][k * 4 + j] = sum;
}

__global__ void attn_kernel(int l) {
    __shared__ float sm0[8], sm1[8];
    int gw = (blockIdx.x * blockDim.x + threadIdx.x) >> 5;
    int lane = threadIdx.x & 31;
    int w = threadIdx.x >> 5;
    float r0 = -3.4e38f, r1 = -3.4e38f;
    if (gw < Nn) {
        float xa = g_xh[(size_t)gw * 64 + lane];
        float xb = g_xh[(size_t)gw * 64 + 32 + lane];
        float4 wa = *(const float4*)&g_ws2[l][lane * 4];
        float4 wb = *(const float4*)&g_ws2[l][(32 + lane) * 4];
        float s0 = xa * wa.x + xb * wb.x;
        float s1 = xa * wa.y + xb * wb.y;
        float d0 = xa * wa.z + xb * wb.z;
        float d1 = xa * wa.w + xb * wb.w;
        s0 = warpReduceSum(s0); s1 = warpReduceSum(s1);
        d0 = warpReduceSum(d0); d1 = warpReduceSum(d1);
        if (lane == 0) {
            g_ad[gw * 2 + 0] = d0; g_ad[gw * 2 + 1] = d1;
            g_nsd[gw] = make_float4(s0, s1, g_dinv[gw], 0.f);
        }
        r0 = s0; r1 = s1;
    }
    if (lane == 0) { sm0[w] = r0; sm1[w] = r1; }
    __syncthreads();
    if (threadIdx.x == 0) {
        float m0 = sm0[0], m1 = sm1[0];
        #pragma unroll
        for (int i = 1; i < 8; ++i) { m0 = fmaxf(m0, sm0[i]); m1 = fmaxf(m1, sm1[i]); }
        atomicMaxF(&g_asmax2[l][0], m0);
        atomicMaxF(&g_asmax2[l][1], m1);
    }
}

__global__ void alpha_kernel(int l) {
    int gw = (blockIdx.x * blockDim.x + threadIdx.x) >> 5;
    int lane = threadIdx.x & 31;
    if (gw >= Nn) return;
    const int rs = g_rowptr[gw], re = g_rowptr[gw + 1];
    const float ad0 = g_ad[2 * gw], ad1 = g_ad[2 * gw + 1];
    const float dinvd = g_nsd[gw].z;
    float m0 = g_asmax2[l][0] + ad0; m0 = m0 > 0.f ? m0 : 0.2f * m0;
    float m1 = g_asmax2[l][1] + ad1; m1 = m1 > 0.f ? m1 : 0.2f * m1;
    for (int i = rs + lane; i < re; i += 32) {
        int2 e = g_csr[i];
        float4 ns = g_nsd[e.x];
        float v0 = ns.x + ad0; v0 = v0 > 0.f ? v0 : 0.2f * v0;
        float v1 = ns.y + ad1; v1 = v1 > 0.f ? v1 : 0.2f * v1;
        float e0 = __expf(v0 - m0);
        float e1 = __expf(v1 - m1);
        float nrm = ns.z * __int_as_float(e.y) * dinvd;
        g_ecoef[i] = make_float4(e0, e1, nrm, __int_as_float(e.x));
    }
}

// ---------------- aggregation: gather-FMA, bf16 hi/lo emission -----------------
__global__ void aggregate_kernel() {
    int gw = (blockIdx.x * blockDim.x + threadIdx.x) >> 5;
    int lane = threadIdx.x & 31;
    if (gw >= Nn) return;
    const int d = gw;
    const int rs = g_rowptr[d], re = g_rowptr[d + 1];

    float s0 = 0.f, s1 = 0.f;
    float a0x = 0.f, a0y = 0.f, a1x = 0.f, a1y = 0.f, sgx = 0.f, sgy = 0.f;
    #pragma unroll 2
    for (int i = rs; i < re; ++i) {
        float4 c = g_ecoef[i];
        int s = __float_as_int(c.w);
        s0 += c.x; s1 += c.y;
        float2 hx = *(const float2*)&g_xh[(size_t)s * 64 + 2 * lane];
        a0x = fmaf(hx.x, c.x, a0x); a0y = fmaf(hx.y, c.x, a0y);
        a1x = fmaf(hx.x, c.y, a1x); a1y = fmaf(hx.y, c.y, a1y);
        sgx = fmaf(hx.x, c.z, sgx); sgy = fmaf(hx.y, c.z, sgy);
    }
    float inv0 = 1.f / fmaxf(s0, 1e-38f);
    float inv1 = 1.f / fmaxf(s1, 1e-38f);
    a0x *= inv0; a0y *= inv0; a1x *= inv1; a1y *= inv1;
    uint32_t h, l;
    uint32_t* agH = (uint32_t*)g_agH4; uint32_t* agL = (uint32_t*)g_agL4;
    uint32_t* sgH = (uint32_t*)g_sgH4; uint32_t* sgL = (uint32_t*)g_sgL4;
    cvt_pair(a0x, a0y, h, l);
    agH[(size_t)d * 64 + lane] = h;      agL[(size_t)d * 64 + lane] = l;
    cvt_pair(a1x, a1y, h, l);
    agH[(size_t)d * 64 + 32 + lane] = h; agL[(size_t)d * 64 + 32 + lane] = l;
    cvt_pair(sgx, sgy, h, l);
    sgH[(size_t)d * 32 + lane] = h;      sgL[(size_t)d * 32 + lane] = l;
}

// ---------------- host orchestration ------------------------------------------
extern "C" void kernel_launch(void* const* d_in, const int* in_sizes, int n_in,
                              void* d_out, int out_size) {
    (void)in_sizes; (void)n_in; (void)out_size;
    const float* x    = (const float*)d_in[0];
    const int*   eidx = (const int*)d_in[1];
    const float* ew   = (const float*)d_in[2];
    const int*   src  = eidx;
    const int*   dst  = eidx + Ee;

    const float* P[2][8];
    for (int l = 0; l < 2; ++l)
        for (int j = 0; j < 8; ++j)
            P[l][j] = (const float*)d_in[3 + l * 8 + j];
    const float* cls_W = (const float*)d_in[19];
    const float* cls_b = (const float*)d_in[20];

    float *p_xh;
    uint4 *p_xH, *p_xL, *p_x2H, *p_x2L, *p_pW0H, *p_pW0L, *p_pW1H, *p_pW1L, *p_cWH, *p_cWL;
    cudaGetSymbolAddress((void**)&p_xh, g_xh);
    cudaGetSymbolAddress((void**)&p_xH, g_xH4);
    cudaGetSymbolAddress((void**)&p_xL, g_xL4);
    cudaGetSymbolAddress((void**)&p_x2H, g_x2H4);
    cudaGetSymbolAddress((void**)&p_x2L, g_x2L4);
    cudaGetSymbolAddress((void**)&p_pW0H, g_pW0H);
    cudaGetSymbolAddress((void**)&p_pW0L, g_pW0L);
    cudaGetSymbolAddress((void**)&p_pW1H, g_pW1H);
    cudaGetSymbolAddress((void**)&p_pW1L, g_pW1L);
    cudaGetSymbolAddress((void**)&p_cWH, g_cWH);
    cudaGetSymbolAddress((void**)&p_cWL, g_cWL);

    // 1: weight transpose+convert  2: x convert  3: hist  4: pre-GEMM0 (profiled)
    tc_all_kernel<<<232, 128>>>(P[0][0], P[1][0], P[0][2], P[1][2], P[0][6], P[1][6], cls_W);
    conv_x_kernel<<<(Nn * 64 + 255) / 256, 256>>>(x);
    hist_kernel<<<(EN + 255) / 256, 256>>>(dst);
    bgemm_kernel<64, 0><<<GEMM_BLKS, 128>>>(
        (const ushort*)p_xH, (const ushort*)p_xL, 256,
        (const ushort*)p_pW0H, (const ushort*)p_pW0L,
        P[0][1], p_xh, nullptr, nullptr, Nn, 256, 64, 0);
    ws_prep_kernel<<<1, 256>>>(0, P[0][2], P[0][3], P[0][4]);
    ws_prep_kernel<<<1, 256>>>(1, P[1][2], P[1][3], P[1][4]);
    scan_block_kernel<<<NB, 1024>>>();
    scan_bsum_kernel<<<1, 128>>>();
    scan_add_kernel<<<(Nn + 255) / 256, 256>>>();
    scatter_kernel<<<(EN + 255) / 256, 256>>>(src, dst, ew);
    deg_csr_kernel<<<WARP_GRID, 256>>>();

    for (int l = 0; l < 2; ++l) {
        if (l == 1) {
            bgemm_kernel<64, 0><<<GEMM_BLKS, 128>>>(
                (const ushort*)p_x2H, (const ushort*)p_x2L, 192,
                (const ushort*)p_pW1H, (const ushort*)p_pW1L,
                P[1][1], p_xh, nullptr, nullptr, Nn, 192, 64, 0);
        }
        attn_kernel<<<WARP_GRID, 256>>>(l);
        alpha_kernel<<<WARP_GRID, 256>>>(l);
        aggregate_kernel<<<WARP_GRID, 256>>>();
        dim3 og(GEMM_BLKS, 3);
        out_bgemm_kernel<<<og, 128>>>(l, P[l][5], P[l][7]);
    }

    // classifier with fused bias + log_softmax -> d_out
    bgemm_kernel<32, 2><<<GEMM_BLKS, 128>>>(
        (const ushort*)p_x2H, (const ushort*)p_x2L, 192,
        (const ushort*)p_cWH, (const ushort*)p_cWL,
        cls_b, (float*)d_out, nullptr, nullptr, Nn, 192, 32, 0);
}

// round 16
// speedup vs baseline: 1.6931x; 1.0780x over previous
#include <cuda_runtime.h>
#include <math.h>
#include <stdint.h>

#define Nn 100000
#define Ee 1200000
#define EN (Ee + Nn)
#define NB ((Nn + 1023) / 1024)        // 98 scan tiles
#define GEMM_BLKS ((Nn + 127) / 128)   // 782
#define WARP_GRID ((Nn * 32 + 255) / 256)

// ---------------- scratch (static; no cudaMalloc) ---------------------------
__device__ float  g_xh[Nn * 64];
__device__ float4 g_nsd[Nn];           // {a_src0, a_src1, dinv, 0}
__device__ float  g_ad[Nn * 2];
__device__ float  g_dinv[Nn];
__device__ float  g_ws2[2][256];
__device__ float  g_asmax2[2][2];

__device__ int    g_cnt[Nn];           // static zero-init; self-cleaned by scan
__device__ int    g_rowptr[Nn + 1];
__device__ int    g_off[Nn];
__device__ int    g_bsum[NB];
__device__ int2   g_csr[EN];

// bf16 hi/lo pools (uint4 for 16B alignment)
__device__ uint4 g_x2H4[Nn * 24], g_x2L4[Nn * 24];   // x2:  [Nn][192]
__device__ uint4 g_agH4[Nn * 16], g_agL4[Nn * 16];   // agg: [Nn][128]
__device__ uint4 g_sgH4[Nn * 8],  g_sgL4[Nn * 8];    // sg:  [Nn][64]
// transposed weights Bt[n][k] bf16 hi/lo
__device__ uint4 g_pW0H[2048], g_pW0L[2048];         // [64][256]
__device__ uint4 g_pW1H[1536], g_pW1L[1536];         // [64][192]
__device__ uint4 g_gWH[2][1024], g_gWL[2][1024];     // [128][64] per layer
__device__ uint4 g_sWH[2][512],  g_sWL[2][512];      // [64][64]  per layer
__device__ uint4 g_cWH[768], g_cWL[768];             // [32][192]

// ---------------- helpers ------------------------------------------------------
__device__ __forceinline__ void atomicMaxF(float* addr, float val) {
    if (val >= 0.f) atomicMax((int*)addr, __float_as_int(val));
    else            atomicMin((unsigned int*)addr, __float_as_uint(val));
}
__device__ __forceinline__ float warpReduceSum(float v) {
    #pragma unroll
    for (int o = 16; o > 0; o >>= 1) v += __shfl_xor_sync(0xffffffffu, v, o);
    return v;
}
__device__ __forceinline__ void cvt_pair(float x0, float x1, uint32_t& h, uint32_t& l) {
    asm("cvt.rn.bf16x2.f32 %0, %1, %2;" : "=r"(h) : "f"(x1), "f"(x0));
    float r0 = x0 - __uint_as_float(h << 16);
    float r1 = x1 - __uint_as_float(h & 0xffff0000u);
    asm("cvt.rn.bf16x2.f32 %0, %1, %2;" : "=r"(l) : "f"(r1), "f"(r0));
}
__device__ __forceinline__ uint32_t cvta_s(const void* p) {
    uint32_t a;
    asm("{.reg .u64 t; cvta.to.shared.u64 t, %1; cvt.u32.u64 %0, t;}" : "=r"(a) : "l"(p));
    return a;
}
__device__ __forceinline__ void cp16(uint32_t s, const void* g) {
    asm volatile("cp.async.cg.shared.global [%0], [%1], 16;" :: "r"(s), "l"(g));
}
__device__ __forceinline__ float2 lds64f(uint32_t a) {
    float2 v;
    asm volatile("ld.shared.v2.f32 {%0,%1},[%2];" : "=f"(v.x), "=f"(v.y) : "r"(a));
    return v;
}
#define CP_COMMIT() asm volatile("cp.async.commit_group;" ::: "memory")
#define CP_WAIT0()  asm volatile("cp.async.wait_group 0;" ::: "memory")
#define LDSM4(r, addr) \
    asm volatile("ldmatrix.sync.aligned.m8n8.x4.shared.b16 {%0,%1,%2,%3}, [%4];" \
        : "=r"((r)[0]), "=r"((r)[1]), "=r"((r)[2]), "=r"((r)[3]) : "r"(addr))
#define MMA16(c, a, b0, b1) \
    asm volatile("mma.sync.aligned.m16n8k16.row.col.f32.bf16.bf16.f32 " \
        "{%0,%1,%2,%3},{%4,%5,%6,%7},{%8,%9},{%0,%1,%2,%3};" \
        : "+f"((c)[0]), "+f"((c)[1]), "+f"((c)[2]), "+f"((c)[3]) \
        : "r"((a)[0]), "r"((a)[1]), "r"((a)[2]), "r"((a)[3]), "r"(b0), "r"(b1))

// ---------------- bf16 split tensor GEMM, cp.async double-buffered ------------
// C = (Ah+Al)[M,K] @ (Bh+Bl)^T, Bt[n][k]. 128 thr, TILE_M=128, BK=32.
// ACVT=0: A is pre-split bf16 hi/lo (AH/AL), ldmatrix fragments.
// ACVT=1: A is fp32; tiles cp.async'd raw, fragments built via LDS64 + cvt_pair.
// MODE 0: float out (+bias). MODE 1: relu -> bf16 hi/lo. MODE 2: bias+log_softmax.
template <int NOUT, int MODE, int ACVT>
__device__ __forceinline__ void bgemm_core(
        const void* __restrict__ AHv, const void* __restrict__ ALv, int lda,
        const ushort* __restrict__ BH, const ushort* __restrict__ BL,
        const float* __restrict__ bias,
        float* __restrict__ Cf, uint32_t* __restrict__ CH, uint32_t* __restrict__ CL,
        int M, int K, int ldc, int col_off) {
    constexpr int NT = NOUT / 8;
    constexpr int BB = (NOUT * 4) / 128;
    constexpr int ABYTES = 128 * 8 * 16;       // 16KB per buffer (both modes)
    constexpr int BBYTES = NOUT * 8 * 16;
    __shared__ uint4 sA[2 * 128 * 8];
    __shared__ uint4 sB[2 * NOUT * 8];

    const ushort* AH = (const ushort*)AHv;
    const ushort* AL = (const ushort*)ALv;
    const float*  AF = (const float*)AHv;

    const int tid = threadIdx.x, lane = tid & 31, wid = tid >> 5;
    const int g = lane >> 2, t4 = lane & 3;
    const int m0 = blockIdx.x * 128;

    float acc[2][NT][4];
    #pragma unroll
    for (int mt = 0; mt < 2; ++mt)
        #pragma unroll
        for (int j = 0; j < NT; ++j)
            #pragma unroll
            for (int i = 0; i < 4; ++i) acc[mt][j][i] = 0.f;

    // A-tile load coords
    int arow[8], ac8[8];
    if (ACVT) {
        #pragma unroll
        for (int it = 0; it < 8; ++it) {       // 1024 chunks of 4 floats
            int idx = tid + it * 128;
            int r = idx >> 3;
            int row = m0 + r; if (row >= M) row = M - 1;
            arow[it] = row; ac8[it] = idx & 7;
        }
    } else {
        #pragma unroll
        for (int it = 0; it < 4; ++it) {       // 512 chunks of 8 ushorts (x2 for lo)
            int idx = tid + it * 128;
            int r = idx >> 2;
            int row = m0 + r; if (row >= M) row = M - 1;
            arow[it] = row; ac8[it] = idx & 3;
        }
    }
    int bn[BB], bc8[BB];
    #pragma unroll
    for (int it = 0; it < BB; ++it) {
        int idx = tid + it * 128;
        bn[it] = idx >> 2; bc8[it] = idx & 3;
    }

    const uint32_t sAa = cvta_s(sA);
    const uint32_t sBa = cvta_s(sB);

    auto issue = [&](int p, int k0) {
        uint32_t bA = sAa + p * ABYTES;
        uint32_t bB = sBa + p * BBYTES;
        if (ACVT) {
            #pragma unroll
            for (int it = 0; it < 8; ++it) {
                int r = (tid + it * 128) >> 3;
                cp16(bA + ((r * 8 + (ac8[it] ^ (r & 7))) << 4),
                     AF + (size_t)arow[it] * lda + k0 + ac8[it] * 4);
            }
        } else {
            #pragma unroll
            for (int it = 0; it < 4; ++it) {
                int r = (tid + it * 128) >> 2;
                size_t o = (size_t)arow[it] * lda + k0 + ac8[it] * 8;
                cp16(bA + ((r * 8 + (ac8[it] ^ (r & 7))) << 4), AH + o);
                cp16(bA + ((r * 8 + ((4 + ac8[it]) ^ (r & 7))) << 4), AL + o);
            }
        }
        #pragma unroll
        for (int it = 0; it < BB; ++it) {
            int n = bn[it];
            size_t o = (size_t)n * K + k0 + bc8[it] * 8;
            cp16(bB + ((n * 8 + (bc8[it] ^ (n & 7))) << 4), BH + o);
            cp16(bB + ((n * 8 + ((4 + bc8[it]) ^ (n & 7))) << 4), BL + o);
        }
        CP_COMMIT();
    };
    auto compute = [&](int p) {
        uint32_t bA = sAa + p * ABYTES;
        uint32_t bB = sBa + p * BBYTES;
        #pragma unroll
        for (int kc = 0; kc < 2; ++kc) {
            uint32_t ah[2][4], al[2][4];
            if (ACVT) {
                // fragments from fp32 smem: row r, kpair p -> chunk p>>1, off (p&1)*8
                #pragma unroll
                for (int mt = 0; mt < 2; ++mt) {
                    int R = wid * 32 + mt * 16;
                    int p0 = 8 * kc + t4, p1 = p0 + 4;
                    int r0 = R + g, r1 = R + 8 + g;
                    float2 v;
                    v = lds64f(bA + ((r0 * 8 + ((p0 >> 1) ^ (r0 & 7))) << 4) + (p0 & 1) * 8);
                    cvt_pair(v.x, v.y, ah[mt][0], al[mt][0]);
                    v = lds64f(bA + ((r1 * 8 + ((p0 >> 1) ^ (r1 & 7))) << 4) + (p0 & 1) * 8);
                    cvt_pair(v.x, v.y, ah[mt][1], al[mt][1]);
                    v = lds64f(bA + ((r0 * 8 + ((p1 >> 1) ^ (r0 & 7))) << 4) + (p1 & 1) * 8);
                    cvt_pair(v.x, v.y, ah[mt][2], al[mt][2]);
                    v = lds64f(bA + ((r1 * 8 + ((p1 >> 1) ^ (r1 & 7))) << 4) + (p1 & 1) * 8);
                    cvt_pair(v.x, v.y, ah[mt][3], al[mt][3]);
                }
            } else {
                int c8 = 2 * kc + (lane >> 4);
                #pragma unroll
                for (int mt = 0; mt < 2; ++mt) {
                    int r = wid * 32 + mt * 16 + (lane & 15);
                    LDSM4(ah[mt], bA + ((r * 8 + (c8 ^ (r & 7))) << 4));
                    LDSM4(al[mt], bA + ((r * 8 + ((4 + c8) ^ (r & 7))) << 4));
                }
            }
            #pragma unroll
            for (int jp = 0; jp < NT / 2; ++jp) {
                int n = 16 * jp + (lane & 7) + ((lane & 16) >> 1);
                int cb = 2 * kc + ((lane >> 3) & 1);
                uint32_t bh[4], bl[4];
                LDSM4(bh, bB + ((n * 8 + (cb ^ (n & 7))) << 4));
                LDSM4(bl, bB + ((n * 8 + ((4 + cb) ^ (n & 7))) << 4));
                #pragma unroll
                for (int mt = 0; mt < 2; ++mt) {
                    MMA16(acc[mt][2 * jp],     ah[mt], bh[0], bh[1]);
                    MMA16(acc[mt][2 * jp],     ah[mt], bl[0], bl[1]);
                    MMA16(acc[mt][2 * jp],     al[mt], bh[0], bh[1]);
                    MMA16(acc[mt][2 * jp + 1], ah[mt], bh[2], bh[3]);
                    MMA16(acc[mt][2 * jp + 1], ah[mt], bl[2], bl[3]);
                    MMA16(acc[mt][2 * jp + 1], al[mt], bh[2], bh[3]);
                }
            }
        }
    };

    issue(0, 0);
    CP_WAIT0();
    __syncthreads();
    int p = 0;
    for (int k0 = 32; k0 < K; k0 += 32) {
        issue(p ^ 1, k0);
        compute(p);
        CP_WAIT0();
        __syncthreads();
        p ^= 1;
    }
    compute(p);

    // -------- epilogues --------
    if (MODE == 2) {
        #pragma unroll
        for (int mt = 0; mt < 2; ++mt) {
            int row0 = m0 + wid * 32 + mt * 16 + g;
            int row1 = row0 + 8;
            float v0[2 * NT], v1[2 * NT];
            #pragma unroll
            for (int j = 0; j < NT; ++j) {
                float b0 = bias[8 * j + 2 * t4], b1 = bias[8 * j + 2 * t4 + 1];
                v0[2 * j] = acc[mt][j][0] + b0; v0[2 * j + 1] = acc[mt][j][1] + b1;
                v1[2 * j] = acc[mt][j][2] + b0; v1[2 * j + 1] = acc[mt][j][3] + b1;
            }
            float m0x = v0[0], m1x = v1[0];
            #pragma unroll
            for (int c = 1; c < 2 * NT; ++c) { m0x = fmaxf(m0x, v0[c]); m1x = fmaxf(m1x, v1[c]); }
            m0x = fmaxf(m0x, __shfl_xor_sync(0xffffffffu, m0x, 1));
            m0x = fmaxf(m0x, __shfl_xor_sync(0xffffffffu, m0x, 2));
            m1x = fmaxf(m1x, __shfl_xor_sync(0xffffffffu, m1x, 1));
            m1x = fmaxf(m1x, __shfl_xor_sync(0xffffffffu, m1x, 2));
            float s0 = 0.f, s1 = 0.f;
            #pragma unroll
            for (int c = 0; c < 2 * NT; ++c) { s0 += expf(v0[c] - m0x); s1 += expf(v1[c] - m1x); }
            s0 += __shfl_xor_sync(0xffffffffu, s0, 1);
            s0 += __shfl_xor_sync(0xffffffffu, s0, 2);
            s1 += __shfl_xor_sync(0xffffffffu, s1, 1);
            s1 += __shfl_xor_sync(0xffffffffu, s1, 2);
            float ls0 = logf(s0) + m0x, ls1 = logf(s1) + m1x;
            #pragma unroll
            for (int j = 0; j < NT; ++j) {
                if (row0 < M)
                    *(float2*)(Cf + (size_t)row0 * 32 + 8 * j + 2 * t4) =
                        make_float2(v0[2 * j] - ls0, v0[2 * j + 1] - ls0);
                if (row1 < M)
                    *(float2*)(Cf + (size_t)row1 * 32 + 8 * j + 2 * t4) =
                        make_float2(v1[2 * j] - ls1, v1[2 * j + 1] - ls1);
            }
        }
        return;
    }

    #pragma unroll
    for (int mt = 0; mt < 2; ++mt) {
        int row0 = m0 + wid * 32 + mt * 16 + g;
        int row1 = row0 + 8;
        #pragma unroll
        for (int j = 0; j < NT; ++j) {
            float b0 = bias ? bias[8 * j + 2 * t4] : 0.f;
            float b1 = bias ? bias[8 * j + 2 * t4 + 1] : 0.f;
            float d0 = acc[mt][j][0] + b0, d1 = acc[mt][j][1] + b1;
            float d2 = acc[mt][j][2] + b0, d3 = acc[mt][j][3] + b1;
            if (MODE == 1) {
                d0 = d0 > 0.f ? d0 : 0.f; d1 = d1 > 0.f ? d1 : 0.f;
                d2 = d2 > 0.f ? d2 : 0.f; d3 = d3 > 0.f ? d3 : 0.f;
                uint32_t h, l;
                if (row0 < M) {
                    cvt_pair(d0, d1, h, l);
                    size_t w = (size_t)row0 * ldc + col_off + 4 * j + t4;
                    CH[w] = h; CL[w] = l;
                }
                if (row1 < M) {
                    cvt_pair(d2, d3, h, l);
                    size_t w = (size_t)row1 * ldc + col_off + 4 * j + t4;
                    CH[w] = h; CL[w] = l;
                }
            } else {
                int col = col_off + 8 * j + 2 * t4;
                if (row0 < M) *(float2*)(Cf + (size_t)row0 * ldc + col) = make_float2(d0, d1);
                if (row1 < M) *(float2*)(Cf + (size_t)row1 * ldc + col) = make_float2(d2, d3);
            }
        }
    }
}

template <int NOUT, int MODE, int ACVT>
__global__ void __launch_bounds__(128, 4)
bgemm_kernel(const void* __restrict__ AH, const void* __restrict__ AL, int lda,
             const ushort* __restrict__ BH, const ushort* __restrict__ BL,
             const float* __restrict__ bias,
             float* __restrict__ Cf, uint32_t* __restrict__ CH, uint32_t* __restrict__ CL,
             int M, int K, int ldc, int col_off) {
    bgemm_core<NOUT, MODE, ACVT>(AH, AL, lda, BH, BL, bias, Cf, CH, CL, M, K, ldc, col_off);
}

// out_gemm: 3 segments via blockIdx.y -> x2 bf16 hi/lo (ldc = 96 words)
__global__ void __launch_bounds__(128, 4)
out_bgemm_kernel(int l, const float* __restrict__ gat_b, const float* __restrict__ sg_b) {
    int seg = blockIdx.y;
    const ushort *AH, *AL, *BH, *BL; const float* bias; int lda, coffw;
    if (seg < 2) {
        AH = (const ushort*)g_agH4 + seg * 64; AL = (const ushort*)g_agL4 + seg * 64; lda = 128;
        BH = (const ushort*)g_gWH[l] + seg * 64 * 64; BL = (const ushort*)g_gWL[l] + seg * 64 * 64;
        bias = gat_b + seg * 64; coffw = seg * 32;
    } else {
        AH = (const ushort*)g_sgH4; AL = (const ushort*)g_sgL4; lda = 64;
        BH = (const ushort*)g_sWH[l]; BL = (const ushort*)g_sWL[l];
        bias = sg_b; coffw = 64;
    }
    bgemm_core<64, 1, 0>(AH, AL, lda, BH, BL, bias,
                         nullptr, (uint32_t*)g_x2H4, (uint32_t*)g_x2L4, Nn, 64, 96, coffw);
}

// ---------------- weight transpose-convert --------------------------------------
__device__ __forceinline__ void tc_one(const float* W, uint32_t* oh, uint32_t* ol,
                                       int K, int N, int widx) {
    int K2 = K / 2;
    if (widx >= N * K2) return;
    int n = widx / K2, kp = widx - n * K2;
    float f0 = W[(2 * kp) * N + n];
    float f1 = W[(2 * kp + 1) * N + n];
    uint32_t h, l;
    cvt_pair(f0, f1, h, l);
    oh[n * K2 + kp] = h;
    ol[n * K2 + kp] = l;
}

__global__ void tc_all_kernel(const float* pW0, const float* pW1,
                              const float* gW0, const float* gW1,
                              const float* sW0, const float* sW1,
                              const float* cW) {
    int b = blockIdx.x, t = threadIdx.x;
    if (b < 64)       tc_one(pW0, (uint32_t*)g_pW0H, (uint32_t*)g_pW0L, 256, 64, (b - 0) * 128 + t);
    else if (b < 112) tc_one(pW1, (uint32_t*)g_pW1H, (uint32_t*)g_pW1L, 192, 64, (b - 64) * 128 + t);
    else if (b < 144) tc_one(gW0, (uint32_t*)g_gWH[0], (uint32_t*)g_gWL[0], 64, 128, (b - 112) * 128 + t);
    else if (b < 176) tc_one(gW1, (uint32_t*)g_gWH[1], (uint32_t*)g_gWL[1], 64, 128, (b - 144) * 128 + t);
    else if (b < 192) tc_one(sW0, (uint32_t*)g_sWH[0], (uint32_t*)g_sWL[0], 64, 64, (b - 176) * 128 + t);
    else if (b < 208) tc_one(sW1, (uint32_t*)g_sWH[1], (uint32_t*)g_sWL[1], 64, 64, (b - 192) * 128 + t);
    else              tc_one(cW,  (uint32_t*)g_cWH,    (uint32_t*)g_cWL,   192, 32, (b - 208) * 128 + t);
}

// ---------------- CSR build -----------------------------------------------------
__global__ void hist_kernel(const int* __restrict__ dst) {
    int e = blockIdx.x * blockDim.x + threadIdx.x;
    if (e >= EN) return;
    int d = (e < Ee) ? dst[e] : e - Ee;
    atomicAdd(&g_cnt[d], 1);
}

__global__ void scan_block_kernel() {
    __shared__ int sh[1024];
    int t = threadIdx.x;
    int i = blockIdx.x * 1024 + t;
    int v = 0;
    if (i < Nn) { v = g_cnt[i]; g_cnt[i] = 0; }
    sh[t] = v;
    __syncthreads();
    #pragma unroll
    for (int o = 1; o < 1024; o <<= 1) {
        int u = (t >= o) ? sh[t - o] : 0;
        __syncthreads();
        sh[t] += u;
        __syncthreads();
    }
    if (i < Nn) g_rowptr[i] = sh[t] - v;
    if (t == 1023) g_bsum[blockIdx.x] = sh[t];
}

__global__ void scan_bsum_kernel() {
    __shared__ int sh[128];
    int t = threadIdx.x;
    int v = (t < NB) ? g_bsum[t] : 0;
    sh[t] = v;
    __syncthreads();
    #pragma unroll
    for (int o = 1; o < 128; o <<= 1) {
        int u = (t >= o) ? sh[t - o] : 0;
        __syncthreads();
        sh[t] += u;
        __syncthreads();
    }
    if (t < NB) g_bsum[t] = sh[t] - v;
}

__global__ void scan_add_kernel() {
    int i = blockIdx.x * blockDim.x + threadIdx.x;
    if (i >= Nn) return;
    int v = g_rowptr[i] + g_bsum[i >> 10];
    g_rowptr[i] = v;
    g_off[i] = v;
    if (i == 0) g_rowptr[Nn] = EN;
}

__global__ void scatter_kernel(const int* __restrict__ src, const int* __restrict__ dst,
                               const float* __restrict__ w) {
    int e = blockIdx.x * blockDim.x + threadIdx.x;
    if (e >= EN) return;
    int s, d; float wt;
    if (e < Ee) { s = src[e]; d = dst[e]; wt = w[e]; }
    else        { s = d = e - Ee; wt = 1.f; }
    int pos = atomicAdd(&g_off[d], 1);
    g_csr[pos] = make_int2(s, __float_as_int(wt));
}

__global__ void deg_csr_kernel() {
    int gw = (blockIdx.x * blockDim.x + threadIdx.x) >> 5;
    int lane = threadIdx.x & 31;
    if (gw >= Nn) return;
    int rs = g_rowptr[gw], re = g_rowptr[gw + 1];
    float sum = 0.f;
    for (int i = rs + lane; i < re; i += 32) sum += __int_as_float(g_csr[i].y);
    sum = warpReduceSum(sum);
    if (lane == 0) g_dinv[gw] = sum > 0.f ? rsqrtf(sum) : 0.f;
}

// ---------------- attention prep / scalars --------------------------------------
__global__ void ws_prep_kernel(int l, const float* __restrict__ gat_W,
                               const float* __restrict__ att_src,
                               const float* __restrict__ att_dst) {
    int t = threadIdx.x;
    if (t == 0) { g_asmax2[l][0] = -3.4e38f; g_asmax2[l][1] = -3.4e38f; }
    int k = t >> 2, j = t & 3;
    int h = j & 1;
    const float* av = (j >> 1) ? att_dst : att_src;
    float sum = 0.f;
    #pragma unroll 8
    for (int c = 0; c < 64; ++c)
        sum = fmaf(gat_W[k * 128 + h * 64 + c], av[h * 64 + c], sum);
    g_ws2[l][k * 4 + j] = sum;
}

__global__ void attn_kernel(int l) {
    __shared__ float sm0[8], sm1[8];
    int gw = (blockIdx.x * blockDim.x + threadIdx.x) >> 5;
    int lane = threadIdx.x & 31;
    int w = threadIdx.x >> 5;
    float r0 = -3.4e38f, r1 = -3.4e38f;
    if (gw < Nn) {
        float xa = g_xh[(size_t)gw * 64 + lane];
        float xb = g_xh[(size_t)gw * 64 + 32 + lane];
        float4 wa = *(const float4*)&g_ws2[l][lane * 4];
        float4 wb = *(const float4*)&g_ws2[l][(32 + lane) * 4];
        float s0 = xa * wa.x + xb * wb.x;
        float s1 = xa * wa.y + xb * wb.y;
        float d0 = xa * wa.z + xb * wb.z;
        float d1 = xa * wa.w + xb * wb.w;
        s0 = warpReduceSum(s0); s1 = warpReduceSum(s1);
        d0 = warpReduceSum(d0); d1 = warpReduceSum(d1);
        if (lane == 0) {
            g_ad[gw * 2 + 0] = d0; g_ad[gw * 2 + 1] = d1;
            g_nsd[gw] = make_float4(s0, s1, g_dinv[gw], 0.f);
        }
        r0 = s0; r1 = s1;
    }
    if (lane == 0) { sm0[w] = r0; sm1[w] = r1; }
    __syncthreads();
    if (threadIdx.x == 0) {
        float m0 = sm0[0], m1 = sm1[0];
        #pragma unroll
        for (int i = 1; i < 8; ++i) { m0 = fmaxf(m0, sm0[i]); m1 = fmaxf(m1, sm1[i]); }
        atomicMaxF(&g_asmax2[l][0], m0);
        atomicMaxF(&g_asmax2[l][1], m1);
    }
}

// ---------------- fused softmax-coef + aggregation (shuffle broadcast) ----------
__global__ void aggregate_kernel(int l) {
    int gw = (blockIdx.x * blockDim.x + threadIdx.x) >> 5;
    int lane = threadIdx.x & 31;
    if (gw >= Nn) return;
    const int d = gw;
    const int rs = g_rowptr[d], re = g_rowptr[d + 1];
    const float ad0 = g_ad[2 * d], ad1 = g_ad[2 * d + 1];
    const float dinvd = g_nsd[d].z;
    float m0 = g_asmax2[l][0] + ad0; m0 = m0 > 0.f ? m0 : 0.2f * m0;
    float m1 = g_asmax2[l][1] + ad1; m1 = m1 > 0.f ? m1 : 0.2f * m1;

    float s0 = 0.f, s1 = 0.f;
    float a0x = 0.f, a0y = 0.f, a1x = 0.f, a1y = 0.f, sgx = 0.f, sgy = 0.f;
    for (int base = rs; base < re; base += 32) {
        int i = base + lane;
        float e0 = 0.f, e1 = 0.f, nrm = 0.f;
        int sv = 0;
        if (i < re) {
            int2 e = g_csr[i];
            float4 ns = g_nsd[e.x];
            float v0 = ns.x + ad0; v0 = v0 > 0.f ? v0 : 0.2f * v0;
            float v1 = ns.y + ad1; v1 = v1 > 0.f ? v1 : 0.2f * v1;
            e0 = __expf(v0 - m0);
            e1 = __expf(v1 - m1);
            nrm = ns.z * __int_as_float(e.y) * dinvd;
            sv = e.x;
        }
        int cnt = re - base; if (cnt > 32) cnt = 32;
        for (int j = 0; j < cnt; ++j) {
            float c0 = __shfl_sync(0xffffffffu, e0, j);
            float c1 = __shfl_sync(0xffffffffu, e1, j);
            float c2 = __shfl_sync(0xffffffffu, nrm, j);
            int   s  = __shfl_sync(0xffffffffu, sv, j);
            s0 += c0; s1 += c1;
            float2 hx = *(const float2*)&g_xh[(size_t)s * 64 + 2 * lane];
            a0x = fmaf(hx.x, c0, a0x); a0y = fmaf(hx.y, c0, a0y);
            a1x = fmaf(hx.x, c1, a1x); a1y = fmaf(hx.y, c1, a1y);
            sgx = fmaf(hx.x, c2, sgx); sgy = fmaf(hx.y, c2, sgy);
        }
    }
    float inv0 = 1.f / fmaxf(s0, 1e-38f);
    float inv1 = 1.f / fmaxf(s1, 1e-38f);
    a0x *= inv0; a0y *= inv0; a1x *= inv1; a1y *= inv1;
    uint32_t h, lw;
    uint32_t* agH = (uint32_t*)g_agH4; uint32_t* agL = (uint32_t*)g_agL4;
    uint32_t* sgH = (uint32_t*)g_sgH4; uint32_t* sgL = (uint32_t*)g_sgL4;
    cvt_pair(a0x, a0y, h, lw);
    agH[(size_t)d * 64 + lane] = h;      agL[(size_t)d * 64 + lane] = lw;
    cvt_pair(a1x, a1y, h, lw);
    agH[(size_t)d * 64 + 32 + lane] = h; agL[(size_t)d * 64 + 32 + lane] = lw;
    cvt_pair(sgx, sgy, h, lw);
    sgH[(size_t)d * 32 + lane] = h;      sgL[(size_t)d * 32 + lane] = lw;
}

// ---------------- host orchestration ------------------------------------------
extern "C" void kernel_launch(void* const* d_in, const int* in_sizes, int n_in,
                              void* d_out, int out_size) {
    (void)in_sizes; (void)n_in; (void)out_size;
    const float* x    = (const float*)d_in[0];
    const int*   eidx = (const int*)d_in[1];
    const float* ew   = (const float*)d_in[2];
    const int*   src  = eidx;
    const int*   dst  = eidx + Ee;

    const float* P[2][8];
    for (int l = 0; l < 2; ++l)
        for (int j = 0; j < 8; ++j)
            P[l][j] = (const float*)d_in[3 + l * 8 + j];
    const float* cls_W = (const float*)d_in[19];
    const float* cls_b = (const float*)d_in[20];

    float *p_xh;
    uint4 *p_x2H, *p_x2L, *p_pW0H, *p_pW0L, *p_pW1H, *p_pW1L, *p_cWH, *p_cWL;
    cudaGetSymbolAddress((void**)&p_xh, g_xh);
    cudaGetSymbolAddress((void**)&p_x2H, g_x2H4);
    cudaGetSymbolAddress((void**)&p_x2L, g_x2L4);
    cudaGetSymbolAddress((void**)&p_pW0H, g_pW0H);
    cudaGetSymbolAddress((void**)&p_pW0L, g_pW0L);
    cudaGetSymbolAddress((void**)&p_pW1H, g_pW1H);
    cudaGetSymbolAddress((void**)&p_pW1L, g_pW1L);
    cudaGetSymbolAddress((void**)&p_cWH, g_cWH);
    cudaGetSymbolAddress((void**)&p_cWL, g_cWL);

    // 1: weights  2: hist  3: ws0  4: pre-GEMM0 w/ inline fp32->bf16 (profiled)
    tc_all_kernel<<<232, 128>>>(P[0][0], P[1][0], P[0][2], P[1][2], P[0][6], P[1][6], cls_W);
    hist_kernel<<<(EN + 255) / 256, 256>>>(dst);
    ws_prep_kernel<<<1, 256>>>(0, P[0][2], P[0][3], P[0][4]);
    bgemm_kernel<64, 0, 1><<<GEMM_BLKS, 128>>>(
        x, nullptr, 256,
        (const ushort*)p_pW0H, (const ushort*)p_pW0L,
        P[0][1], p_xh, nullptr, nullptr, Nn, 256, 64, 0);
    ws_prep_kernel<<<1, 256>>>(1, P[1][2], P[1][3], P[1][4]);
    scan_block_kernel<<<NB, 1024>>>();
    scan_bsum_kernel<<<1, 128>>>();
    scan_add_kernel<<<(Nn + 255) / 256, 256>>>();
    scatter_kernel<<<(EN + 255) / 256, 256>>>(src, dst, ew);
    deg_csr_kernel<<<WARP_GRID, 256>>>();

    for (int l = 0; l < 2; ++l) {
        if (l == 1) {
            bgemm_kernel<64, 0, 0><<<GEMM_BLKS, 128>>>(
                p_x2H, p_x2L, 192,
                (const ushort*)p_pW1H, (const ushort*)p_pW1L,
                P[1][1], p_xh, nullptr, nullptr, Nn, 192, 64, 0);
        }
        attn_kernel<<<WARP_GRID, 256>>>(l);
        aggregate_kernel<<<WARP_GRID, 256>>>(l);
        dim3 og(GEMM_BLKS, 3);
        out_bgemm_kernel<<<og, 128>>>(l, P[l][5], P[l][7]);
    }

    // classifier with fused bias + log_softmax -> d_out
    bgemm_kernel<32, 2, 0><<<GEMM_BLKS, 128>>>(
        p_x2H, p_x2L, 192,
        (const ushort*)p_cWH, (const ushort*)p_cWL,
        cls_b, (float*)d_out, nullptr, nullptr, Nn, 192, 32, 0);
}

// round 17
// speedup vs baseline: 1.7666x; 1.0434x over previous
#include <cuda_runtime.h>
#include <math.h>
#include <stdint.h>

#define Nn 100000
#define Ee 1200000
#define EN (Ee + Nn)
#define NB ((Nn + 1023) / 1024)        // 98 scan tiles
#define GEMM_BLKS ((Nn + 127) / 128)   // 782
#define WARP_GRID ((Nn * 32 + 255) / 256)

// ---------------- scratch (static; no cudaMalloc) ---------------------------
__device__ float  g_xh[Nn * 64];
__device__ float4 g_nsd[Nn];           // {a_src0, a_src1, dinv, 0}
__device__ float  g_ad[Nn * 2];
__device__ float  g_dinv[Nn];
__device__ float  g_ws2[2][256];
__device__ float  g_asmax2[2][2];

__device__ int    g_cnt[Nn];           // static zero-init; self-cleaned by scan
__device__ int    g_rowptr[Nn + 1];
__device__ int    g_off[Nn];
__device__ int    g_bsum[NB];
__device__ int2   g_csr[EN];

// bf16 hi/lo pools (uint4 for 16B alignment)
__device__ uint4 g_x2H4[Nn * 24], g_x2L4[Nn * 24];   // x2:  [Nn][192]
__device__ uint4 g_agH4[Nn * 16], g_agL4[Nn * 16];   // agg: [Nn][128]
__device__ uint4 g_sgH4[Nn * 8],  g_sgL4[Nn * 8];    // sg:  [Nn][64]
// transposed weights Bt[n][k] bf16 hi/lo
__device__ uint4 g_pW0H[2048], g_pW0L[2048];         // [64][256]
__device__ uint4 g_pW1H[1536], g_pW1L[1536];         // [64][192]
__device__ uint4 g_gWH[2][1024], g_gWL[2][1024];     // [128][64] per layer
__device__ uint4 g_sWH[2][512],  g_sWL[2][512];      // [64][64]  per layer
__device__ uint4 g_cWH[768], g_cWL[768];             // [32][192]

// ---------------- helpers ------------------------------------------------------
__device__ __forceinline__ void atomicMaxF(float* addr, float val) {
    if (val >= 0.f) atomicMax((int*)addr, __float_as_int(val));
    else            atomicMin((unsigned int*)addr, __float_as_uint(val));
}
__device__ __forceinline__ float warpReduceSum(float v) {
    #pragma unroll
    for (int o = 16; o > 0; o >>= 1) v += __shfl_xor_sync(0xffffffffu, v, o);
    return v;
}
__device__ __forceinline__ void cvt_pair(float x0, float x1, uint32_t& h, uint32_t& l) {
    asm("cvt.rn.bf16x2.f32 %0, %1, %2;" : "=r"(h) : "f"(x1), "f"(x0));
    float r0 = x0 - __uint_as_float(h << 16);
    float r1 = x1 - __uint_as_float(h & 0xffff0000u);
    asm("cvt.rn.bf16x2.f32 %0, %1, %2;" : "=r"(l) : "f"(r1), "f"(r0));
}
__device__ __forceinline__ uint32_t cvta_s(const void* p) {
    uint32_t a;
    asm("{.reg .u64 t; cvta.to.shared.u64 t, %1; cvt.u32.u64 %0, t;}" : "=r"(a) : "l"(p));
    return a;
}
__device__ __forceinline__ void cp16(uint32_t s, const void* g) {
    asm volatile("cp.async.cg.shared.global [%0], [%1], 16;" :: "r"(s), "l"(g));
}
__device__ __forceinline__ float2 lds64f(uint32_t a) {
    float2 v;
    asm volatile("ld.shared.v2.f32 {%0,%1},[%2];" : "=f"(v.x), "=f"(v.y) : "r"(a));
    return v;
}
#define CP_COMMIT() asm volatile("cp.async.commit_group;" ::: "memory")
#define CP_WAIT0()  asm volatile("cp.async.wait_group 0;" ::: "memory")
#define LDSM4(r, addr) \
    asm volatile("ldmatrix.sync.aligned.m8n8.x4.shared.b16 {%0,%1,%2,%3}, [%4];" \
        : "=r"((r)[0]), "=r"((r)[1]), "=r"((r)[2]), "=r"((r)[3]) : "r"(addr))
#define MMA16(c, a, b0, b1) \
    asm volatile("mma.sync.aligned.m16n8k16.row.col.f32.bf16.bf16.f32 " \
        "{%0,%1,%2,%3},{%4,%5,%6,%7},{%8,%9},{%0,%1,%2,%3};" \
        : "+f"((c)[0]), "+f"((c)[1]), "+f"((c)[2]), "+f"((c)[3]) \
        : "r"((a)[0]), "r"((a)[1]), "r"((a)[2]), "r"((a)[3]), "r"(b0), "r"(b1))

// ---------------- bf16 split tensor GEMM, cp.async double-buffered ------------
template <int NOUT, int MODE, int ACVT>
__device__ __forceinline__ void bgemm_core(
        const void* __restrict__ AHv, const void* __restrict__ ALv, int lda,
        const ushort* __restrict__ BH, const ushort* __restrict__ BL,
        const float* __restrict__ bias,
        float* __restrict__ Cf, uint32_t* __restrict__ CH, uint32_t* __restrict__ CL,
        int M, int K, int ldc, int col_off) {
    constexpr int NT = NOUT / 8;
    constexpr int BB = (NOUT * 4) / 128;
    constexpr int ABYTES = 128 * 8 * 16;
    constexpr int BBYTES = NOUT * 8 * 16;
    __shared__ uint4 sA[2 * 128 * 8];
    __shared__ uint4 sB[2 * NOUT * 8];

    const ushort* AH = (const ushort*)AHv;
    const ushort* AL = (const ushort*)ALv;
    const float*  AF = (const float*)AHv;

    const int tid = threadIdx.x, lane = tid & 31, wid = tid >> 5;
    const int g = lane >> 2, t4 = lane & 3;
    const int m0 = blockIdx.x * 128;

    float acc[2][NT][4];
    #pragma unroll
    for (int mt = 0; mt < 2; ++mt)
        #pragma unroll
        for (int j = 0; j < NT; ++j)
            #pragma unroll
            for (int i = 0; i < 4; ++i) acc[mt][j][i] = 0.f;

    int arow[8], ac8[8];
    if (ACVT) {
        #pragma unroll
        for (int it = 0; it < 8; ++it) {
            int idx = tid + it * 128;
            int r = idx >> 3;
            int row = m0 + r; if (row >= M) row = M - 1;
            arow[it] = row; ac8[it] = idx & 7;
        }
    } else {
        #pragma unroll
        for (int it = 0; it < 4; ++it) {
            int idx = tid + it * 128;
            int r = idx >> 2;
            int row = m0 + r; if (row >= M) row = M - 1;
            arow[it] = row; ac8[it] = idx & 3;
        }
    }
    int bn[BB], bc8[BB];
    #pragma unroll
    for (int it = 0; it < BB; ++it) {
        int idx = tid + it * 128;
        bn[it] = idx >> 2; bc8[it] = idx & 3;
    }

    const uint32_t sAa = cvta_s(sA);
    const uint32_t sBa = cvta_s(sB);

    auto issue = [&](int p, int k0) {
        uint32_t bA = sAa + p * ABYTES;
        uint32_t bB = sBa + p * BBYTES;
        if (ACVT) {
            #pragma unroll
            for (int it = 0; it < 8; ++it) {
                int r = (tid + it * 128) >> 3;
                cp16(bA + ((r * 8 + (ac8[it] ^ (r & 7))) << 4),
                     AF + (size_t)arow[it] * lda + k0 + ac8[it] * 4);
            }
        } else {
            #pragma unroll
            for (int it = 0; it < 4; ++it) {
                int r = (tid + it * 128) >> 2;
                size_t o = (size_t)arow[it] * lda + k0 + ac8[it] * 8;
                cp16(bA + ((r * 8 + (ac8[it] ^ (r & 7))) << 4), AH + o);
                cp16(bA + ((r * 8 + ((4 + ac8[it]) ^ (r & 7))) << 4), AL + o);
            }
        }
        #pragma unroll
        for (int it = 0; it < BB; ++it) {
            int n = bn[it];
            size_t o = (size_t)n * K + k0 + bc8[it] * 8;
            cp16(bB + ((n * 8 + (bc8[it] ^ (n & 7))) << 4), BH + o);
            cp16(bB + ((n * 8 + ((4 + bc8[it]) ^ (n & 7))) << 4), BL + o);
        }
        CP_COMMIT();
    };
    auto compute = [&](int p) {
        uint32_t bA = sAa + p * ABYTES;
        uint32_t bB = sBa + p * BBYTES;
        #pragma unroll
        for (int kc = 0; kc < 2; ++kc) {
            uint32_t ah[2][4], al[2][4];
            if (ACVT) {
                #pragma unroll
                for (int mt = 0; mt < 2; ++mt) {
                    int R = wid * 32 + mt * 16;
                    int p0 = 8 * kc + t4, p1 = p0 + 4;
                    int r0 = R + g, r1 = R + 8 + g;
                    float2 v;
                    v = lds64f(bA + ((r0 * 8 + ((p0 >> 1) ^ (r0 & 7))) << 4) + (p0 & 1) * 8);
                    cvt_pair(v.x, v.y, ah[mt][0], al[mt][0]);
                    v = lds64f(bA + ((r1 * 8 + ((p0 >> 1) ^ (r1 & 7))) << 4) + (p0 & 1) * 8);
                    cvt_pair(v.x, v.y, ah[mt][1], al[mt][1]);
                    v = lds64f(bA + ((r0 * 8 + ((p1 >> 1) ^ (r0 & 7))) << 4) + (p1 & 1) * 8);
                    cvt_pair(v.x, v.y, ah[mt][2], al[mt][2]);
                    v = lds64f(bA + ((r1 * 8 + ((p1 >> 1) ^ (r1 & 7))) << 4) + (p1 & 1) * 8);
                    cvt_pair(v.x, v.y, ah[mt][3], al[mt][3]);
                }
            } else {
                int c8 = 2 * kc + (lane >> 4);
                #pragma unroll
                for (int mt = 0; mt < 2; ++mt) {
                    int r = wid * 32 + mt * 16 + (lane & 15);
                    LDSM4(ah[mt], bA + ((r * 8 + (c8 ^ (r & 7))) << 4));
                    LDSM4(al[mt], bA + ((r * 8 + ((4 + c8) ^ (r & 7))) << 4));
                }
            }
            #pragma unroll
            for (int jp = 0; jp < NT / 2; ++jp) {
                int n = 16 * jp + (lane & 7) + ((lane & 16) >> 1);
                int cb = 2 * kc + ((lane >> 3) & 1);
                uint32_t bh[4], bl[4];
                LDSM4(bh, bB + ((n * 8 + (cb ^ (n & 7))) << 4));
                LDSM4(bl, bB + ((n * 8 + ((4 + cb) ^ (n & 7))) << 4));
                #pragma unroll
                for (int mt = 0; mt < 2; ++mt) {
                    MMA16(acc[mt][2 * jp],     ah[mt], bh[0], bh[1]);
                    MMA16(acc[mt][2 * jp],     ah[mt], bl[0], bl[1]);
                    MMA16(acc[mt][2 * jp],     al[mt], bh[0], bh[1]);
                    MMA16(acc[mt][2 * jp + 1], ah[mt], bh[2], bh[3]);
                    MMA16(acc[mt][2 * jp + 1], ah[mt], bl[2], bl[3]);
                    MMA16(acc[mt][2 * jp + 1], al[mt], bh[2], bh[3]);
                }
            }
        }
    };

    issue(0, 0);
    CP_WAIT0();
    __syncthreads();
    int p = 0;
    for (int k0 = 32; k0 < K; k0 += 32) {
        issue(p ^ 1, k0);
        compute(p);
        CP_WAIT0();
        __syncthreads();
        p ^= 1;
    }
    compute(p);

    if (MODE == 2) {
        #pragma unroll
        for (int mt = 0; mt < 2; ++mt) {
            int row0 = m0 + wid * 32 + mt * 16 + g;
            int row1 = row0 + 8;
            float v0[2 * NT], v1[2 * NT];
            #pragma unroll
            for (int j = 0; j < NT; ++j) {
                float b0 = bias[8 * j + 2 * t4], b1 = bias[8 * j + 2 * t4 + 1];
                v0[2 * j] = acc[mt][j][0] + b0; v0[2 * j + 1] = acc[mt][j][1] + b1;
                v1[2 * j] = acc[mt][j][2] + b0; v1[2 * j + 1] = acc[mt][j][3] + b1;
            }
            float m0x = v0[0], m1x = v1[0];
            #pragma unroll
            for (int c = 1; c < 2 * NT; ++c) { m0x = fmaxf(m0x, v0[c]); m1x = fmaxf(m1x, v1[c]); }
            m0x = fmaxf(m0x, __shfl_xor_sync(0xffffffffu, m0x, 1));
            m0x = fmaxf(m0x, __shfl_xor_sync(0xffffffffu, m0x, 2));
            m1x = fmaxf(m1x, __shfl_xor_sync(0xffffffffu, m1x, 1));
            m1x = fmaxf(m1x, __shfl_xor_sync(0xffffffffu, m1x, 2));
            float s0 = 0.f, s1 = 0.f;
            #pragma unroll
            for (int c = 0; c < 2 * NT; ++c) { s0 += expf(v0[c] - m0x); s1 += expf(v1[c] - m1x); }
            s0 += __shfl_xor_sync(0xffffffffu, s0, 1);
            s0 += __shfl_xor_sync(0xffffffffu, s0, 2);
            s1 += __shfl_xor_sync(0xffffffffu, s1, 1);
            s1 += __shfl_xor_sync(0xffffffffu, s1, 2);
            float ls0 = logf(s0) + m0x, ls1 = logf(s1) + m1x;
            #pragma unroll
            for (int j = 0; j < NT; ++j) {
                if (row0 < M)
                    *(float2*)(Cf + (size_t)row0 * 32 + 8 * j + 2 * t4) =
                        make_float2(v0[2 * j] - ls0, v0[2 * j + 1] - ls0);
                if (row1 < M)
                    *(float2*)(Cf + (size_t)row1 * 32 + 8 * j + 2 * t4) =
                        make_float2(v1[2 * j] - ls1, v1[2 * j + 1] - ls1);
            }
        }
        return;
    }

    #pragma unroll
    for (int mt = 0; mt < 2; ++mt) {
        int row0 = m0 + wid * 32 + mt * 16 + g;
        int row1 = row0 + 8;
        #pragma unroll
        for (int j = 0; j < NT; ++j) {
            float b0 = bias ? bias[8 * j + 2 * t4] : 0.f;
            float b1 = bias ? bias[8 * j + 2 * t4 + 1] : 0.f;
            float d0 = acc[mt][j][0] + b0, d1 = acc[mt][j][1] + b1;
            float d2 = acc[mt][j][2] + b0, d3 = acc[mt][j][3] + b1;
            if (MODE == 1) {
                d0 = d0 > 0.f ? d0 : 0.f; d1 = d1 > 0.f ? d1 : 0.f;
                d2 = d2 > 0.f ? d2 : 0.f; d3 = d3 > 0.f ? d3 : 0.f;
                uint32_t h, l;
                if (row0 < M) {
                    cvt_pair(d0, d1, h, l);
                    size_t w = (size_t)row0 * ldc + col_off + 4 * j + t4;
                    CH[w] = h; CL[w] = l;
                }
                if (row1 < M) {
                    cvt_pair(d2, d3, h, l);
                    size_t w = (size_t)row1 * ldc + col_off + 4 * j + t4;
                    CH[w] = h; CL[w] = l;
                }
            } else {
                int col = col_off + 8 * j + 2 * t4;
                if (row0 < M) *(float2*)(Cf + (size_t)row0 * ldc + col) = make_float2(d0, d1);
                if (row1 < M) *(float2*)(Cf + (size_t)row1 * ldc + col) = make_float2(d2, d3);
            }
        }
    }
}

template <int NOUT, int MODE, int ACVT>
__global__ void __launch_bounds__(128, 4)
bgemm_kernel(const void* __restrict__ AH, const void* __restrict__ AL, int lda,
             const ushort* __restrict__ BH, const ushort* __restrict__ BL,
             const float* __restrict__ bias,
             float* __restrict__ Cf, uint32_t* __restrict__ CH, uint32_t* __restrict__ CL,
             int M, int K, int ldc, int col_off) {
    bgemm_core<NOUT, MODE, ACVT>(AH, AL, lda, BH, BL, bias, Cf, CH, CL, M, K, ldc, col_off);
}

__global__ void __launch_bounds__(128, 4)
out_bgemm_kernel(int l, const float* __restrict__ gat_b, const float* __restrict__ sg_b) {
    int seg = blockIdx.y;
    const ushort *AH, *AL, *BH, *BL; const float* bias; int lda, coffw;
    if (seg < 2) {
        AH = (const ushort*)g_agH4 + seg * 64; AL = (const ushort*)g_agL4 + seg * 64; lda = 128;
        BH = (const ushort*)g_gWH[l] + seg * 64 * 64; BL = (const ushort*)g_gWL[l] + seg * 64 * 64;
        bias = gat_b + seg * 64; coffw = seg * 32;
    } else {
        AH = (const ushort*)g_sgH4; AL = (const ushort*)g_sgL4; lda = 64;
        BH = (const ushort*)g_sWH[l]; BL = (const ushort*)g_sWL[l];
        bias = sg_b; coffw = 64;
    }
    bgemm_core<64, 1, 0>(AH, AL, lda, BH, BL, bias,
                         nullptr, (uint32_t*)g_x2H4, (uint32_t*)g_x2L4, Nn, 64, 96, coffw);
}

// ---------------- weight transpose-convert --------------------------------------
__device__ __forceinline__ void tc_one(const float* W, uint32_t* oh, uint32_t* ol,
                                       int K, int N, int widx) {
    int K2 = K / 2;
    if (widx >= N * K2) return;
    int n = widx / K2, kp = widx - n * K2;
    float f0 = W[(2 * kp) * N + n];
    float f1 = W[(2 * kp + 1) * N + n];
    uint32_t h, l;
    cvt_pair(f0, f1, h, l);
    oh[n * K2 + kp] = h;
    ol[n * K2 + kp] = l;
}

__global__ void tc_all_kernel(const float* pW0, const float* pW1,
                              const float* gW0, const float* gW1,
                              const float* sW0, const float* sW1,
                              const float* cW) {
    int b = blockIdx.x, t = threadIdx.x;
    if (b < 64)       tc_one(pW0, (uint32_t*)g_pW0H, (uint32_t*)g_pW0L, 256, 64, (b - 0) * 128 + t);
    else if (b < 112) tc_one(pW1, (uint32_t*)g_pW1H, (uint32_t*)g_pW1L, 192, 64, (b - 64) * 128 + t);
    else if (b < 144) tc_one(gW0, (uint32_t*)g_gWH[0], (uint32_t*)g_gWL[0], 64, 128, (b - 112) * 128 + t);
    else if (b < 176) tc_one(gW1, (uint32_t*)g_gWH[1], (uint32_t*)g_gWL[1], 64, 128, (b - 144) * 128 + t);
    else if (b < 192) tc_one(sW0, (uint32_t*)g_sWH[0], (uint32_t*)g_sWL[0], 64, 64, (b - 176) * 128 + t);
    else if (b < 208) tc_one(sW1, (uint32_t*)g_sWH[1], (uint32_t*)g_sWL[1], 64, 64, (b - 192) * 128 + t);
    else              tc_one(cW,  (uint32_t*)g_cWH,    (uint32_t*)g_cWL,   192, 32, (b - 208) * 128 + t);
}

// ---------------- CSR build -----------------------------------------------------
__global__ void hist_kernel(const int* __restrict__ dst) {
    int e = blockIdx.x * blockDim.x + threadIdx.x;
    if (e >= EN) return;
    int d = (e < Ee) ? dst[e] : e - Ee;
    atomicAdd(&g_cnt[d], 1);
}

__global__ void scan_block_kernel() {
    __shared__ int sh[1024];
    int t = threadIdx.x;
    int i = blockIdx.x * 1024 + t;
    int v = 0;
    if (i < Nn) { v = g_cnt[i]; g_cnt[i] = 0; }
    sh[t] = v;
    __syncthreads();
    #pragma unroll
    for (int o = 1; o < 1024; o <<= 1) {
        int u = (t >= o) ? sh[t - o] : 0;
        __syncthreads();
        sh[t] += u;
        __syncthreads();
    }
    if (i < Nn) g_rowptr[i] = sh[t] - v;
    if (t == 1023) g_bsum[blockIdx.x] = sh[t];
}

__global__ void scan_bsum_kernel() {
    __shared__ int sh[128];
    int t = threadIdx.x;
    int v = (t < NB) ? g_bsum[t] : 0;
    sh[t] = v;
    __syncthreads();
    #pragma unroll
    for (int o = 1; o < 128; o <<= 1) {
        int u = (t >= o) ? sh[t - o] : 0;
        __syncthreads();
        sh[t] += u;
        __syncthreads();
    }
    if (t < NB) g_bsum[t] = sh[t] - v;
}

__global__ void scan_add_kernel() {
    int i = blockIdx.x * blockDim.x + threadIdx.x;
    if (i >= Nn) return;
    int v = g_rowptr[i] + g_bsum[i >> 10];
    g_rowptr[i] = v;
    g_off[i] = v;
    if (i == 0) g_rowptr[Nn] = EN;
}

__global__ void scatter_kernel(const int* __restrict__ src, const int* __restrict__ dst,
                               const float* __restrict__ w) {
    int e = blockIdx.x * blockDim.x + threadIdx.x;
    if (e >= EN) return;
    int s, d; float wt;
    if (e < Ee) { s = src[e]; d = dst[e]; wt = w[e]; }
    else        { s = d = e - Ee; wt = 1.f; }
    int pos = atomicAdd(&g_off[d], 1);
    g_csr[pos] = make_int2(s, __float_as_int(wt));
}

__global__ void deg_csr_kernel() {
    int gw = (blockIdx.x * blockDim.x + threadIdx.x) >> 5;
    int lane = threadIdx.x & 31;
    if (gw >= Nn) return;
    int rs = g_rowptr[gw], re = g_rowptr[gw + 1];
    float sum = 0.f;
    for (int i = rs + lane; i < re; i += 32) sum += __int_as_float(g_csr[i].y);
    sum = warpReduceSum(sum);
    if (lane == 0) g_dinv[gw] = sum > 0.f ? rsqrtf(sum) : 0.f;
}

// ---------------- attention prep / scalars --------------------------------------
__global__ void ws_prep_kernel(int l, const float* __restrict__ gat_W,
                               const float* __restrict__ att_src,
                               const float* __restrict__ att_dst) {
    int t = threadIdx.x;
    if (t == 0) { g_asmax2[l][0] = -3.4e38f; g_asmax2[l][1] = -3.4e38f; }
    int k = t >> 2, j = t & 3;
    int h = j & 1;
    const float* av = (j >> 1) ? att_dst : att_src;
    float sum = 0.f;
    #pragma unroll 8
    for (int c = 0; c < 64; ++c)
        sum = fmaf(gat_W[k * 128 + h * 64 + c], av[h * 64 + c], sum);
    g_ws2[l][k * 4 + j] = sum;
}

__global__ void attn_kernel(int l) {
    __shared__ float sm0[8], sm1[8];
    int gw = (blockIdx.x * blockDim.x + threadIdx.x) >> 5;
    int lane = threadIdx.x & 31;
    int w = threadIdx.x >> 5;
    float r0 = -3.4e38f, r1 = -3.4e38f;
    if (gw < Nn) {
        float xa = g_xh[(size_t)gw * 64 + lane];
        float xb = g_xh[(size_t)gw * 64 + 32 + lane];
        float4 wa = *(const float4*)&g_ws2[l][lane * 4];
        float4 wb = *(const float4*)&g_ws2[l][(32 + lane) * 4];
        float s0 = xa * wa.x + xb * wb.x;
        float s1 = xa * wa.y + xb * wb.y;
        float d0 = xa * wa.z + xb * wb.z;
        float d1 = xa * wa.w + xb * wb.w;
        s0 = warpReduceSum(s0); s1 = warpReduceSum(s1);
        d0 = warpReduceSum(d0); d1 = warpReduceSum(d1);
        if (lane == 0) {
            g_ad[gw * 2 + 0] = d0; g_ad[gw * 2 + 1] = d1;
            g_nsd[gw] = make_float4(s0, s1, g_dinv[gw], 0.f);
        }
        r0 = s0; r1 = s1;
    }
    if (lane == 0) { sm0[w] = r0; sm1[w] = r1; }
    __syncthreads();
    if (threadIdx.x == 0) {
        float m0 = sm0[0], m1 = sm1[0];
        #pragma unroll
        for (int i = 1; i < 8; ++i) { m0 = fmaxf(m0, sm0[i]); m1 = fmaxf(m1, sm1[i]); }
        atomicMaxF(&g_asmax2[l][0], m0);
        atomicMaxF(&g_asmax2[l][1], m1);
    }
}

// ---------------- fused softmax-coef + aggregation (shuffle broadcast) ----------
__global__ void aggregate_kernel(int l) {
    int gw = (blockIdx.x * blockDim.x + threadIdx.x) >> 5;
    int lane = threadIdx.x & 31;
    if (gw >= Nn) return;
    const int d = gw;
    const int rs = g_rowptr[d], re = g_rowptr[d + 1];
    const float ad0 = g_ad[2 * d], ad1 = g_ad[2 * d + 1];
    const float dinvd = g_nsd[d].z;
    float m0 = g_asmax2[l][0] + ad0; m0 = m0 > 0.f ? m0 : 0.2f * m0;
    float m1 = g_asmax2[l][1] + ad1; m1 = m1 > 0.f ? m1 : 0.2f * m1;

    float s0 = 0.f, s1 = 0.f;
    float a0x = 0.f, a0y = 0.f, a1x = 0.f, a1y = 0.f, sgx = 0.f, sgy = 0.f;
    for (int base = rs; base < re; base += 32) {
        int i = base + lane;
        float e0 = 0.f, e1 = 0.f, nrm = 0.f;
        int sv = 0;
        if (i < re) {
            int2 e = g_csr[i];
            float4 ns = g_nsd[e.x];
            float v0 = ns.x + ad0; v0 = v0 > 0.f ? v0 : 0.2f * v0;
            float v1 = ns.y + ad1; v1 = v1 > 0.f ? v1 : 0.2f * v1;
            e0 = __expf(v0 - m0);
            e1 = __expf(v1 - m1);
            nrm = ns.z * __int_as_float(e.y) * dinvd;
            sv = e.x;
        }
        int cnt = re - base; if (cnt > 32) cnt = 32;
        for (int j = 0; j < cnt; ++j) {
            float c0 = __shfl_sync(0xffffffffu, e0, j);
            float c1 = __shfl_sync(0xffffffffu, e1, j);
            float c2 = __shfl_sync(0xffffffffu, nrm, j);
            int   s  = __shfl_sync(0xffffffffu, sv, j);
            s0 += c0; s1 += c1;
            float2 hx = *(const float2*)&g_xh[(size_t)s * 64 + 2 * lane];
            a0x = fmaf(hx.x, c0, a0x); a0y = fmaf(hx.y, c0, a0y);
            a1x = fmaf(hx.x, c1, a1x); a1y = fmaf(hx.y, c1, a1y);
            sgx = fmaf(hx.x, c2, sgx); sgy = fmaf(hx.y, c2, sgy);
        }
    }
    float inv0 = 1.f / fmaxf(s0, 1e-38f);
    float inv1 = 1.f / fmaxf(s1, 1e-38f);
    a0x *= inv0; a0y *= inv0; a1x *= inv1; a1y *= inv1;
    uint32_t h, lw;
    uint32_t* agH = (uint32_t*)g_agH4; uint32_t* agL = (uint32_t*)g_agL4;
    uint32_t* sgH = (uint32_t*)g_sgH4; uint32_t* sgL = (uint32_t*)g_sgL4;
    cvt_pair(a0x, a0y, h, lw);
    agH[(size_t)d * 64 + lane] = h;      agL[(size_t)d * 64 + lane] = lw;
    cvt_pair(a1x, a1y, h, lw);
    agH[(size_t)d * 64 + 32 + lane] = h; agL[(size_t)d * 64 + 32 + lane] = lw;
    cvt_pair(sgx, sgy, h, lw);
    sgH[(size_t)d * 32 + lane] = h;      sgL[(size_t)d * 32 + lane] = lw;
}

// ---------------- host orchestration ------------------------------------------
extern "C" void kernel_launch(void* const* d_in, const int* in_sizes, int n_in,
                              void* d_out, int out_size) {
    (void)in_sizes; (void)n_in; (void)out_size;
    const float* x    = (const float*)d_in[0];
    const int*   eidx = (const int*)d_in[1];
    const float* ew   = (const float*)d_in[2];
    const int*   src  = eidx;
    const int*   dst  = eidx + Ee;

    const float* P[2][8];
    for (int l = 0; l < 2; ++l)
        for (int j = 0; j < 8; ++j)
            P[l][j] = (const float*)d_in[3 + l * 8 + j];
    const float* cls_W = (const float*)d_in[19];
    const float* cls_b = (const float*)d_in[20];

    float *p_xh;
    uint4 *p_x2H, *p_x2L, *p_pW0H, *p_pW0L, *p_pW1H, *p_pW1L, *p_cWH, *p_cWL;
    cudaGetSymbolAddress((void**)&p_xh, g_xh);
    cudaGetSymbolAddress((void**)&p_x2H, g_x2H4);
    cudaGetSymbolAddress((void**)&p_x2L, g_x2L4);
    cudaGetSymbolAddress((void**)&p_pW0H, g_pW0H);
    cudaGetSymbolAddress((void**)&p_pW0L, g_pW0L);
    cudaGetSymbolAddress((void**)&p_pW1H, g_pW1H);
    cudaGetSymbolAddress((void**)&p_pW1L, g_pW1L);
    cudaGetSymbolAddress((void**)&p_cWH, g_cWH);
    cudaGetSymbolAddress((void**)&p_cWL, g_cWL);

    // forked side stream for the CSR chain (independent of the GEMM-prep chain).
    // Created fresh per call (kernel_launch runs only a few times; graph replays
    // don't re-enter this function). Fork/join via events is capture-legal.
    cudaStream_t s2;
    cudaStreamCreateWithFlags(&s2, cudaStreamNonBlocking);
    cudaEvent_t evF, evJ;
    cudaEventCreateWithFlags(&evF, cudaEventDisableTiming);
    cudaEventCreateWithFlags(&evJ, cudaEventDisableTiming);

    cudaEventRecord(evF, 0);
    cudaStreamWaitEvent(s2, evF, 0);
    // --- side stream: CSR build ---
    hist_kernel<<<(EN + 255) / 256, 256, 0, s2>>>(dst);
    scan_block_kernel<<<NB, 1024, 0, s2>>>();
    scan_bsum_kernel<<<1, 128, 0, s2>>>();
    scan_add_kernel<<<(Nn + 255) / 256, 256, 0, s2>>>();
    scatter_kernel<<<(EN + 255) / 256, 256, 0, s2>>>(src, dst, ew);
    deg_csr_kernel<<<WARP_GRID, 256, 0, s2>>>();
    cudaEventRecord(evJ, s2);

    // --- main stream: weight prep + pre-GEMM0 ---
    tc_all_kernel<<<232, 128>>>(P[0][0], P[1][0], P[0][2], P[1][2], P[0][6], P[1][6], cls_W);
    ws_prep_kernel<<<1, 256>>>(0, P[0][2], P[0][3], P[0][4]);
    bgemm_kernel<64, 0, 1><<<GEMM_BLKS, 128>>>(
        x, nullptr, 256,
        (const ushort*)p_pW0H, (const ushort*)p_pW0L,
        P[0][1], p_xh, nullptr, nullptr, Nn, 256, 64, 0);
    ws_prep_kernel<<<1, 256>>>(1, P[1][2], P[1][3], P[1][4]);

    // join: attn needs g_dinv; aggregate needs CSR
    cudaStreamWaitEvent(0, evJ, 0);

    for (int l = 0; l < 2; ++l) {
        if (l == 1) {
            bgemm_kernel<64, 0, 0><<<GEMM_BLKS, 128>>>(
                p_x2H, p_x2L, 192,
                (const ushort*)p_pW1H, (const ushort*)p_pW1L,
                P[1][1], p_xh, nullptr, nullptr, Nn, 192, 64, 0);
        }
        attn_kernel<<<WARP_GRID, 256>>>(l);
        aggregate_kernel<<<WARP_GRID, 256>>>(l);
        dim3 og(GEMM_BLKS, 3);
        out_bgemm_kernel<<<og, 128>>>(l, P[l][5], P[l][7]);
    }

    // classifier with fused bias + log_softmax -> d_out
    bgemm_kernel<32, 2, 0><<<GEMM_BLKS, 128>>>(
        p_x2H, p_x2L, 192,
        (const ushort*)p_cWH, (const ushort*)p_cWL,
        cls_b, (float*)d_out, nullptr, nullptr, Nn, 192, 32, 0);
}